// round 7
// baseline (speedup 1.0000x reference)
#include <cuda_runtime.h>
#include <math_constants.h>

#define B_  8
#define S_  2048
#define D_  512
#define H_  8
#define DH_ 64
#define M_  (B_*S_)   // 16384
#define NT_ (S_/64)   // 32 key tiles
#define QT_ 128       // q-rows per attention CTA

// Scratch (allocation-free rule: __device__ globals)
__device__ float g_Q[B_*H_*S_*DH_];
__device__ float g_K[B_*H_*S_*DH_];
__device__ float g_V[B_*H_*S_*DH_];
__device__ float g_O[M_*D_];
__device__ float g_X[M_*D_];        // tf32-rounded x
__device__ float g_Wi[3*D_*D_];     // tf32-rounded w_in
__device__ float g_Wo[D_*D_];       // tf32-rounded w_out

// ---------------------------------------------------------------------------
// helpers
// ---------------------------------------------------------------------------
__device__ __forceinline__ unsigned tf32u(float x) {
    unsigned u;
    asm("cvt.rna.tf32.f32 %0, %1;" : "=r"(u) : "f"(x));
    return u;
}
__device__ __forceinline__ float tf32f(float x) { return __uint_as_float(tf32u(x)); }
__device__ __forceinline__ unsigned fu(float x) { return __float_as_uint(x); }
__device__ __forceinline__ float ex2f(float x) {
    float y;
    asm("ex2.approx.f32 %0, %1;" : "=f"(y) : "f"(x));
    return y;
}

__device__ __forceinline__ void mma8(float* c, const unsigned* a, const unsigned* b) {
    asm volatile(
        "mma.sync.aligned.m16n8k8.row.col.f32.tf32.tf32.f32 "
        "{%0,%1,%2,%3}, {%4,%5,%6,%7}, {%8,%9}, {%0,%1,%2,%3};"
        : "+f"(c[0]), "+f"(c[1]), "+f"(c[2]), "+f"(c[3])
        : "r"(a[0]), "r"(a[1]), "r"(a[2]), "r"(a[3]), "r"(b[0]), "r"(b[1]));
}

// 4-matrix ldmatrix: for tf32, each m8n8.b16 matrix = 8 rows x 4 tf32 cols.
__device__ __forceinline__ void ldsm4(unsigned* r, unsigned addr) {
    asm volatile("ldmatrix.sync.aligned.m8n8.x4.shared.b16 {%0,%1,%2,%3}, [%4];"
                 : "=r"(r[0]), "=r"(r[1]), "=r"(r[2]), "=r"(r[3]) : "r"(addr));
}

__device__ __forceinline__ unsigned sptr(const void* p) {
    return (unsigned)__cvta_generic_to_shared(p);
}
#define CP16(d, s)  asm volatile("cp.async.cg.shared.global [%0], [%1], 16;\n" :: "r"(d), "l"(s))
#define CPCOMMIT    asm volatile("cp.async.commit_group;\n")
#define CPWAIT1     asm volatile("cp.async.wait_group 1;\n")
#define CPWAIT0     asm volatile("cp.async.wait_group 0;\n")

// ---------------------------------------------------------------------------
// tf32 pre-round (elementwise, float4)
// ---------------------------------------------------------------------------
__global__ void round_kernel(const float4* __restrict__ in, float4* __restrict__ out, int n4) {
    int i = blockIdx.x * 256 + threadIdx.x;
    if (i < n4) {
        float4 v = in[i];
        out[i] = make_float4(tf32f(v.x), tf32f(v.y), tf32f(v.z), tf32f(v.w));
    }
}

// ---------------------------------------------------------------------------
// QKV projection: g_X[16384,512] @ g_Wi^T + b -> scatter tf32-rounded to Q,K,V
// 128x128 tile, 256 threads, k-chunk 32, 2-stage cp.async, LDSM fragments.
// Q scaled by 0.125*log2(e) so softmax runs in exp2 domain.
// ---------------------------------------------------------------------------
#define GP 36
#define GST (128*GP)   // 4608 floats per stage

__global__ __launch_bounds__(256, 2) void qkv_kernel(const float* __restrict__ bias) {
    extern __shared__ float sm[];
    float* As = sm;              // 2 stages
    float* Bs = sm + 2*GST;

    int tid = threadIdx.x;
    int m0 = blockIdx.y * 128, n0 = blockIdx.x * 128;
    int w = tid >> 5, lane = tid & 31;
    int wm = w >> 1, wn = w & 1;
    int g = lane >> 2, tg = lane & 3;
    int lr = tid >> 3, lc4 = (tid & 7) * 4;
    int l8 = lane & 7, b3 = (lane >> 3) & 1, b4 = lane >> 4;

    const float* X = g_X;
    const float* W = g_Wi;

    // LDSM base byte-addresses (stage 0, kb 0)
    unsigned aA[2], aB[4];
#pragma unroll
    for (int mt = 0; mt < 2; mt++)
        aA[mt] = sptr(As) + ((wm*32 + mt*16 + l8 + b3*8) * GP + b4*4) * 4;
#pragma unroll
    for (int p = 0; p < 4; p++)
        aB[p] = sptr(Bs) + ((wn*64 + (2*p + b4)*8 + l8) * GP + b3*4) * 4;

#define QKV_ISSUE(kc, stg) do {                                               \
        _Pragma("unroll")                                                     \
        for (int p = 0; p < 4; p++) {                                         \
            int row = lr + p * 32;                                            \
            CP16(sptr(&As[(stg)*GST + row*GP + lc4]),                         \
                 X + (size_t)(m0 + row) * D_ + (kc) + lc4);                   \
            CP16(sptr(&Bs[(stg)*GST + row*GP + lc4]),                         \
                 W + (size_t)(n0 + row) * D_ + (kc) + lc4);                   \
        }                                                                     \
        CPCOMMIT;                                                             \
    } while (0)

    QKV_ISSUE(0, 0);

    float acc[2][8][4];
#pragma unroll
    for (int mt = 0; mt < 2; mt++)
#pragma unroll
        for (int nt = 0; nt < 8; nt++)
#pragma unroll
            for (int i = 0; i < 4; i++) acc[mt][nt][i] = 0.f;

    for (int kci = 0; kci < 16; kci++) {
        int cur = kci & 1;
        if (kci + 1 < 16) { QKV_ISSUE((kci + 1) * 32, cur ^ 1); CPWAIT1; }
        else              { CPWAIT0; }
        __syncthreads();
        unsigned sb = cur * (GST * 4);
#pragma unroll
        for (int ks = 0; ks < 4; ks++) {
            unsigned kbb = sb + ks * 32;
            unsigned a0[4], a1[4];
            ldsm4(a0, aA[0] + kbb);
            ldsm4(a1, aA[1] + kbb);
#pragma unroll
            for (int p = 0; p < 4; p++) {
                unsigned bb[4];
                ldsm4(bb, aB[p] + kbb);
                mma8(acc[0][2*p],   a0, bb);
                mma8(acc[1][2*p],   a1, bb);
                mma8(acc[0][2*p+1], a0, bb + 2);
                mma8(acc[1][2*p+1], a1, bb + 2);
            }
        }
        __syncthreads();
    }

    int sec = n0 >> 9;
    float* dst = (sec == 0) ? g_Q : (sec == 1 ? g_K : g_V);
    // Q carries 1/sqrt(Dh) * log2(e): softmax becomes pure ex2
    float qs = (sec == 0) ? 0.125f * 1.4426950408889634f : 1.0f;
#pragma unroll
    for (int mt = 0; mt < 2; mt++) {
#pragma unroll
        for (int half = 0; half < 2; half++) {
            int mm = m0 + wm * 32 + mt * 16 + g + half * 8;
            int bb = mm >> 11, ss = mm & (S_ - 1);
#pragma unroll
            for (int nt = 0; nt < 8; nt++) {
                int col = n0 + wn * 64 + nt * 8 + 2 * tg;
                float2 bi = *(const float2*)(bias + col);
                float v0 = tf32f((acc[mt][nt][half * 2 + 0] + bi.x) * qs);
                float v1 = tf32f((acc[mt][nt][half * 2 + 1] + bi.y) * qs);
                int d = col & (D_ - 1);
                int hh = d >> 6, dh = d & 63;
                float* p = dst + (((size_t)(bb * H_ + hh)) * S_ + ss) * DH_ + dh;
                *(float2*)p = make_float2(v0, v1);
            }
        }
    }
}

// ---------------------------------------------------------------------------
// Flash attention, tf32 mma, cp.async pipelined, LDSM fragments (Q, K, P).
// CTA = 128 q-rows, 128 threads (4 warps x 32 q-rows = 2 m-frags each).
// exp2-domain softmax. V natural layout, scalar B-frags (pitch 72, no conflicts).
// ---------------------------------------------------------------------------
#define QP 68
#define KP 68
#define VP 72

__global__ __launch_bounds__(128, 2) void attn_kernel() {
    extern __shared__ float sm[];
    float* SP = sm;                  // 128 x 68 : Q, then P
    float* KB = sm + QT_ * QP;       // 64 x 68
    float* VB = KB + 64 * KP;        // 64 x 72

    int qt = blockIdx.x, h = blockIdx.y, b = blockIdx.z;
    const float* Qg = g_Q + (((size_t)(b * H_ + h)) * S_ + qt * QT_) * DH_;
    const float* Kg = g_K + ((size_t)(b * H_ + h)) * S_ * DH_;
    const float* Vg = g_V + ((size_t)(b * H_ + h)) * S_ * DH_;

    int tid = threadIdx.x, w = tid >> 5, lane = tid & 31;
    int g = lane >> 2, tg = lane & 3;
    int l8 = lane & 7, b3 = (lane >> 3) & 1, b4 = lane >> 4;
    int r0 = w * 32;                 // warp owns rows [r0, r0+32)

    // LDSM base addresses
    unsigned aSP[2], aK[4];
#pragma unroll
    for (int f = 0; f < 2; f++)
        aSP[f] = sptr(SP) + ((r0 + f*16 + l8 + b3*8) * QP + b4*4) * 4;
#pragma unroll
    for (int p = 0; p < 4; p++)
        aK[p] = sptr(KB) + (((2*p + b4)*8 + l8) * KP + b3*4) * 4;

    // prologue: Q(128x64) -> SP ; K0 -> KB
#pragma unroll
    for (int p = 0; p < 16; p++) {
        int slot = tid + p * 128, row = slot >> 4, c4 = (slot & 15) * 4;
        CP16(sptr(&SP[row * QP + c4]), Qg + row * DH_ + c4);
    }
    CPCOMMIT;
#pragma unroll
    for (int p = 0; p < 8; p++) {
        int slot = tid + p * 128, row = slot >> 4, c4 = (slot & 15) * 4;
        CP16(sptr(&KB[row * KP + c4]), Kg + row * DH_ + c4);
    }
    CPCOMMIT;
    CPWAIT1;          // Q ready (K0 in flight)
    __syncthreads();

    // cache Q A-fragments: 2 m-frags x 8 k-steps (LDSM)
    unsigned qf[2][8][4];
#pragma unroll
    for (int f = 0; f < 2; f++)
#pragma unroll
        for (int ks = 0; ks < 8; ks++)
            ldsm4(qf[f][ks], aSP[f] + ks * 32);

    float oacc[2][8][4];
#pragma unroll
    for (int f = 0; f < 2; f++)
#pragma unroll
        for (int dt = 0; dt < 8; dt++)
#pragma unroll
            for (int i = 0; i < 4; i++) oacc[f][dt][i] = 0.f;
    float mrow[2][2], lrow[2][2];
#pragma unroll
    for (int f = 0; f < 2; f++) {
        mrow[f][0] = -CUDART_INF_F; mrow[f][1] = -CUDART_INF_F;
        lrow[f][0] = 0.f; lrow[f][1] = 0.f;
    }

    for (int kt = 0; kt < NT_; kt++) {
        // issue V[kt]
        const float* Vt = Vg + (size_t)kt * 64 * DH_;
#pragma unroll
        for (int p = 0; p < 8; p++) {
            int slot = tid + p * 128, row = slot >> 4, c4 = (slot & 15) * 4;
            CP16(sptr(&VB[row * VP + c4]), Vt + row * DH_ + c4);
        }
        CPCOMMIT;
        CPWAIT1;              // K[kt] ready (V[kt] in flight)
        __syncthreads();

        // S = Q K^T for both m-frags, LDSM B-frags (2 n-tiles per LDSM)
        float s[2][8][4];
#pragma unroll
        for (int f = 0; f < 2; f++)
#pragma unroll
            for (int nt = 0; nt < 8; nt++)
#pragma unroll
                for (int i = 0; i < 4; i++) s[f][nt][i] = 0.f;
#pragma unroll
        for (int ks = 0; ks < 8; ks++) {
            unsigned kbb = ks * 32;
#pragma unroll
            for (int p = 0; p < 4; p++) {
                unsigned bb[4];
                ldsm4(bb, aK[p] + kbb);
                mma8(s[0][2*p],   qf[0][ks], bb);
                mma8(s[1][2*p],   qf[1][ks], bb);
                mma8(s[0][2*p+1], qf[0][ks], bb + 2);
                mma8(s[1][2*p+1], qf[1][ks], bb + 2);
            }
        }
        __syncthreads();      // KB free

        // prefetch K[kt+1] — overlaps softmax + PV
        const float* Kt = Kg + (size_t)((kt + 1) & (NT_ - 1)) * 64 * DH_;
#pragma unroll
        for (int p = 0; p < 8; p++) {
            int slot = tid + p * 128, row = slot >> 4, c4 = (slot & 15) * 4;
            CP16(sptr(&KB[row * KP + c4]), Kt + row * DH_ + c4);
        }
        CPCOMMIT;

        // online softmax (exp2 domain — Q carries log2e)
#pragma unroll
        for (int f = 0; f < 2; f++) {
            float mxl = -CUDART_INF_F, mxh = -CUDART_INF_F;
#pragma unroll
            for (int nt = 0; nt < 8; nt++) {
                mxl = fmaxf(mxl, fmaxf(s[f][nt][0], s[f][nt][1]));
                mxh = fmaxf(mxh, fmaxf(s[f][nt][2], s[f][nt][3]));
            }
            mxl = fmaxf(mxl, __shfl_xor_sync(0xffffffffu, mxl, 1));
            mxl = fmaxf(mxl, __shfl_xor_sync(0xffffffffu, mxl, 2));
            mxh = fmaxf(mxh, __shfl_xor_sync(0xffffffffu, mxh, 1));
            mxh = fmaxf(mxh, __shfl_xor_sync(0xffffffffu, mxh, 2));
            float mnl = fmaxf(mrow[f][0], mxl), mnh = fmaxf(mrow[f][1], mxh);
            float al = ex2f(mrow[f][0] - mnl), ah = ex2f(mrow[f][1] - mnh);
            mrow[f][0] = mnl; mrow[f][1] = mnh;
            float rsl = 0.f, rsh = 0.f;
#pragma unroll
            for (int nt = 0; nt < 8; nt++) {
                s[f][nt][0] = ex2f(s[f][nt][0] - mnl);
                s[f][nt][1] = ex2f(s[f][nt][1] - mnl);
                s[f][nt][2] = ex2f(s[f][nt][2] - mnh);
                s[f][nt][3] = ex2f(s[f][nt][3] - mnh);
                rsl += s[f][nt][0] + s[f][nt][1];
                rsh += s[f][nt][2] + s[f][nt][3];
            }
            rsl += __shfl_xor_sync(0xffffffffu, rsl, 1);
            rsl += __shfl_xor_sync(0xffffffffu, rsl, 2);
            rsh += __shfl_xor_sync(0xffffffffu, rsh, 1);
            rsh += __shfl_xor_sync(0xffffffffu, rsh, 2);
            lrow[f][0] = lrow[f][0] * al + rsl;
            lrow[f][1] = lrow[f][1] * ah + rsh;
#pragma unroll
            for (int dt = 0; dt < 8; dt++) {
                oacc[f][dt][0] *= al; oacc[f][dt][1] *= al;
                oacc[f][dt][2] *= ah; oacc[f][dt][3] *= ah;
            }
            // publish P rows for this frag
            int rl = r0 + f * 16 + g, rh = rl + 8;
#pragma unroll
            for (int nt = 0; nt < 8; nt++) {
                int c = nt * 8 + 2 * tg;
                *(float2*)&SP[rl * QP + c] = make_float2(tf32f(s[f][nt][0]), tf32f(s[f][nt][1]));
                *(float2*)&SP[rh * QP + c] = make_float2(tf32f(s[f][nt][2]), tf32f(s[f][nt][3]));
            }
        }

        CPWAIT1;              // V[kt] ready (K[kt+1] in flight)
        __syncthreads();

        // O += P V : LDSM P A-frags, scalar V B-frags (shared across m-frags)
#pragma unroll
        for (int ks = 0; ks < 8; ks++) {
            int kb = ks * 8;
            unsigned pa[2][4];
            ldsm4(pa[0], aSP[0] + ks * 32);
            ldsm4(pa[1], aSP[1] + ks * 32);
#pragma unroll
            for (int dt = 0; dt < 8; dt++) {
                unsigned bb[2];
                bb[0] = fu(VB[(kb + tg) * VP + dt * 8 + g]);
                bb[1] = fu(VB[(kb + tg + 4) * VP + dt * 8 + g]);
                mma8(oacc[0][dt], pa[0], bb);
                mma8(oacc[1][dt], pa[1], bb);
            }
        }
        __syncthreads();      // VB free before next V issue
    }

    // epilogue
    float* Og = g_O + ((size_t)(b * S_ + qt * QT_)) * D_ + h * DH_;
#pragma unroll
    for (int f = 0; f < 2; f++) {
        float il = 1.0f / lrow[f][0], ih = 1.0f / lrow[f][1];
        int rl = r0 + f * 16 + g, rh = rl + 8;
#pragma unroll
        for (int dt = 0; dt < 8; dt++) {
            int c = dt * 8 + 2 * tg;
            *(float2*)&Og[(size_t)rl * D_ + c] =
                make_float2(tf32f(oacc[f][dt][0] * il), tf32f(oacc[f][dt][1] * il));
            *(float2*)&Og[(size_t)rh * D_ + c] =
                make_float2(tf32f(oacc[f][dt][2] * ih), tf32f(oacc[f][dt][3] * ih));
        }
    }
}

// ---------------------------------------------------------------------------
// Output projection: g_O[16384,512] @ g_Wo^T + b_out -> out (fp32)
// ---------------------------------------------------------------------------
__global__ __launch_bounds__(256, 2) void out_kernel(const float* __restrict__ bias,
                                                     float* __restrict__ out) {
    extern __shared__ float sm[];
    float* As = sm;
    float* Bs = sm + 2*GST;

    int tid = threadIdx.x;
    int m0 = blockIdx.y * 128, n0 = blockIdx.x * 128;
    int w = tid >> 5, lane = tid & 31;
    int wm = w >> 1, wn = w & 1;
    int g = lane >> 2, tg = lane & 3;
    int lr = tid >> 3, lc4 = (tid & 7) * 4;
    int l8 = lane & 7, b3 = (lane >> 3) & 1, b4 = lane >> 4;

    const float* X = g_O;
    const float* W = g_Wo;

    unsigned aA[2], aB[4];
#pragma unroll
    for (int mt = 0; mt < 2; mt++)
        aA[mt] = sptr(As) + ((wm*32 + mt*16 + l8 + b3*8) * GP + b4*4) * 4;
#pragma unroll
    for (int p = 0; p < 4; p++)
        aB[p] = sptr(Bs) + ((wn*64 + (2*p + b4)*8 + l8) * GP + b3*4) * 4;

#define OUT_ISSUE(kc, stg) do {                                               \
        _Pragma("unroll")                                                     \
        for (int p = 0; p < 4; p++) {                                         \
            int row = lr + p * 32;                                            \
            CP16(sptr(&As[(stg)*GST + row*GP + lc4]),                         \
                 X + (size_t)(m0 + row) * D_ + (kc) + lc4);                   \
            CP16(sptr(&Bs[(stg)*GST + row*GP + lc4]),                         \
                 W + (size_t)(n0 + row) * D_ + (kc) + lc4);                   \
        }                                                                     \
        CPCOMMIT;                                                             \
    } while (0)

    OUT_ISSUE(0, 0);

    float acc[2][8][4];
#pragma unroll
    for (int mt = 0; mt < 2; mt++)
#pragma unroll
        for (int nt = 0; nt < 8; nt++)
#pragma unroll
            for (int i = 0; i < 4; i++) acc[mt][nt][i] = 0.f;

    for (int kci = 0; kci < 16; kci++) {
        int cur = kci & 1;
        if (kci + 1 < 16) { OUT_ISSUE((kci + 1) * 32, cur ^ 1); CPWAIT1; }
        else              { CPWAIT0; }
        __syncthreads();
        unsigned sb = cur * (GST * 4);
#pragma unroll
        for (int ks = 0; ks < 4; ks++) {
            unsigned kbb = sb + ks * 32;
            unsigned a0[4], a1[4];
            ldsm4(a0, aA[0] + kbb);
            ldsm4(a1, aA[1] + kbb);
#pragma unroll
            for (int p = 0; p < 4; p++) {
                unsigned bb[4];
                ldsm4(bb, aB[p] + kbb);
                mma8(acc[0][2*p],   a0, bb);
                mma8(acc[1][2*p],   a1, bb);
                mma8(acc[0][2*p+1], a0, bb + 2);
                mma8(acc[1][2*p+1], a1, bb + 2);
            }
        }
        __syncthreads();
    }

#pragma unroll
    for (int mt = 0; mt < 2; mt++) {
#pragma unroll
        for (int half = 0; half < 2; half++) {
            int mm = m0 + wm * 32 + mt * 16 + g + half * 8;
#pragma unroll
            for (int nt = 0; nt < 8; nt++) {
                int col = n0 + wn * 64 + nt * 8 + 2 * tg;
                float2 bi = *(const float2*)(bias + col);
                *(float2*)&out[(size_t)mm * D_ + col] =
                    make_float2(acc[mt][nt][half * 2 + 0] + bi.x,
                                acc[mt][nt][half * 2 + 1] + bi.y);
            }
        }
    }
}

// ---------------------------------------------------------------------------
extern "C" void kernel_launch(void* const* d_in, const int* in_sizes, int n_in,
                              void* d_out, int out_size) {
    const float* x     = (const float*)d_in[0];
    const float* w_in  = (const float*)d_in[1];
    const float* b_in  = (const float*)d_in[2];
    const float* w_out = (const float*)d_in[3];
    const float* b_out = (const float*)d_in[4];
    float* out = (float*)d_out;

    const int gemm_smem = 4 * GST * 4;                          // 73728 B
    const int attn_smem = (QT_*QP + 64*KP + 64*VP) * 4;         // 70656 B
    cudaFuncSetAttribute(qkv_kernel,  cudaFuncAttributeMaxDynamicSharedMemorySize, gemm_smem);
    cudaFuncSetAttribute(out_kernel,  cudaFuncAttributeMaxDynamicSharedMemorySize, gemm_smem);
    cudaFuncSetAttribute(attn_kernel, cudaFuncAttributeMaxDynamicSharedMemorySize, attn_smem);

    float* gx;  cudaGetSymbolAddress((void**)&gx,  g_X);
    float* gwi; cudaGetSymbolAddress((void**)&gwi, g_Wi);
    float* gwo; cudaGetSymbolAddress((void**)&gwo, g_Wo);
    round_kernel<<<(M_*D_/4 + 255)/256, 256>>>((const float4*)x,     (float4*)gx,  M_*D_/4);
    round_kernel<<<(3*D_*D_/4 + 255)/256, 256>>>((const float4*)w_in,  (float4*)gwi, 3*D_*D_/4);
    round_kernel<<<(D_*D_/4 + 255)/256, 256>>>((const float4*)w_out, (float4*)gwo, D_*D_/4);

    qkv_kernel<<<dim3(12, 128), 256, gemm_smem>>>(b_in);
    attn_kernel<<<dim3(S_ / QT_, H_, B_), 128, attn_smem>>>();
    out_kernel<<<dim3(4, 128), 256, gemm_smem>>>(b_out, out);
}

// round 8
// speedup vs baseline: 1.0886x; 1.0886x over previous
#include <cuda_runtime.h>
#include <math_constants.h>

#define B_  8
#define S_  2048
#define D_  512
#define H_  8
#define DH_ 64
#define M_  (B_*S_)   // 16384
#define NT_ (S_/64)   // 32 key tiles
#define QT_ 128       // q-rows per attention CTA

// Scratch (allocation-free rule: __device__ globals)
__device__ float g_Q[B_*H_*S_*DH_];
__device__ float g_K[B_*H_*S_*DH_];
__device__ float g_V[B_*H_*S_*DH_];
__device__ float g_O[M_*D_];
__device__ float g_X[M_*D_];        // tf32-rounded x
__device__ float g_Wi[3*D_*D_];     // tf32-rounded w_in
__device__ float g_Wo[D_*D_];       // tf32-rounded w_out

// ---------------------------------------------------------------------------
// helpers
// ---------------------------------------------------------------------------
__device__ __forceinline__ unsigned tf32u(float x) {
    unsigned u;
    asm("cvt.rna.tf32.f32 %0, %1;" : "=r"(u) : "f"(x));
    return u;
}
__device__ __forceinline__ float tf32f(float x) { return __uint_as_float(tf32u(x)); }
__device__ __forceinline__ unsigned fu(float x) { return __float_as_uint(x); }
__device__ __forceinline__ float ex2f(float x) {
    float y;
    asm("ex2.approx.f32 %0, %1;" : "=f"(y) : "f"(x));
    return y;
}

__device__ __forceinline__ void mma8(float* c, const unsigned* a, const unsigned* b) {
    asm volatile(
        "mma.sync.aligned.m16n8k8.row.col.f32.tf32.tf32.f32 "
        "{%0,%1,%2,%3}, {%4,%5,%6,%7}, {%8,%9}, {%0,%1,%2,%3};"
        : "+f"(c[0]), "+f"(c[1]), "+f"(c[2]), "+f"(c[3])
        : "r"(a[0]), "r"(a[1]), "r"(a[2]), "r"(a[3]), "r"(b[0]), "r"(b[1]));
}

// 4-matrix ldmatrix: for tf32, each m8n8.b16 matrix = 8 rows x 4 tf32 cols.
__device__ __forceinline__ void ldsm4(unsigned* r, unsigned addr) {
    asm volatile("ldmatrix.sync.aligned.m8n8.x4.shared.b16 {%0,%1,%2,%3}, [%4];"
                 : "=r"(r[0]), "=r"(r[1]), "=r"(r[2]), "=r"(r[3]) : "r"(addr));
}

__device__ __forceinline__ unsigned sptr(const void* p) {
    return (unsigned)__cvta_generic_to_shared(p);
}
#define CP16(d, s)  asm volatile("cp.async.cg.shared.global [%0], [%1], 16;\n" :: "r"(d), "l"(s))
#define CPCOMMIT    asm volatile("cp.async.commit_group;\n")
#define CPWAIT1     asm volatile("cp.async.wait_group 1;\n")
#define CPWAIT0     asm volatile("cp.async.wait_group 0;\n")

// ---------------------------------------------------------------------------
// tf32 pre-round: all three tensors in one launch
// ---------------------------------------------------------------------------
#define XN4  (M_*D_/4)
#define WIN4 (3*D_*D_/4)
#define WON4 (D_*D_/4)

__global__ void round_kernel(const float4* __restrict__ x,
                             const float4* __restrict__ wi,
                             const float4* __restrict__ wo,
                             float4* __restrict__ gx,
                             float4* __restrict__ gwi,
                             float4* __restrict__ gwo) {
    int i = blockIdx.x * 256 + threadIdx.x;
    const float4* src; float4* dst; int j;
    if (i < XN4)               { src = x;  dst = gx;  j = i; }
    else if (i < XN4 + WIN4)   { src = wi; dst = gwi; j = i - XN4; }
    else if (i < XN4+WIN4+WON4){ src = wo; dst = gwo; j = i - XN4 - WIN4; }
    else return;
    float4 v = src[j];
    dst[j] = make_float4(tf32f(v.x), tf32f(v.y), tf32f(v.z), tf32f(v.w));
}

// ---------------------------------------------------------------------------
// QKV projection: g_X[16384,512] @ g_Wi^T + b -> scatter tf32-rounded to Q,K,V
// 128x128 tile, 256 threads, k-chunk 32, 2-stage cp.async, LDSM fragments.
// Q scaled by 0.125*log2(e) so softmax runs in exp2 domain.
// ---------------------------------------------------------------------------
#define GP 36
#define GST (128*GP)   // 4608 floats per stage

__global__ __launch_bounds__(256, 2) void qkv_kernel(const float* __restrict__ bias) {
    extern __shared__ float sm[];
    float* As = sm;              // 2 stages
    float* Bs = sm + 2*GST;

    int tid = threadIdx.x;
    int m0 = blockIdx.y * 128, n0 = blockIdx.x * 128;
    int w = tid >> 5, lane = tid & 31;
    int wm = w >> 1, wn = w & 1;
    int g = lane >> 2, tg = lane & 3;
    int lr = tid >> 3, lc4 = (tid & 7) * 4;
    int l8 = lane & 7, b3 = (lane >> 3) & 1, b4 = lane >> 4;

    const float* X = g_X;
    const float* W = g_Wi;

    unsigned aA[2], aB[4];
#pragma unroll
    for (int mt = 0; mt < 2; mt++)
        aA[mt] = sptr(As) + ((wm*32 + mt*16 + l8 + b3*8) * GP + b4*4) * 4;
#pragma unroll
    for (int p = 0; p < 4; p++)
        aB[p] = sptr(Bs) + ((wn*64 + (2*p + b4)*8 + l8) * GP + b3*4) * 4;

#define QKV_ISSUE(kc, stg) do {                                               \
        _Pragma("unroll")                                                     \
        for (int p = 0; p < 4; p++) {                                         \
            int row = lr + p * 32;                                            \
            CP16(sptr(&As[(stg)*GST + row*GP + lc4]),                         \
                 X + (size_t)(m0 + row) * D_ + (kc) + lc4);                   \
            CP16(sptr(&Bs[(stg)*GST + row*GP + lc4]),                         \
                 W + (size_t)(n0 + row) * D_ + (kc) + lc4);                   \
        }                                                                     \
        CPCOMMIT;                                                             \
    } while (0)

    QKV_ISSUE(0, 0);

    float acc[2][8][4];
#pragma unroll
    for (int mt = 0; mt < 2; mt++)
#pragma unroll
        for (int nt = 0; nt < 8; nt++)
#pragma unroll
            for (int i = 0; i < 4; i++) acc[mt][nt][i] = 0.f;

    for (int kci = 0; kci < 16; kci++) {
        int cur = kci & 1;
        if (kci + 1 < 16) { QKV_ISSUE((kci + 1) * 32, cur ^ 1); CPWAIT1; }
        else              { CPWAIT0; }
        __syncthreads();
        unsigned sb = cur * (GST * 4);
#pragma unroll
        for (int ks = 0; ks < 4; ks++) {
            unsigned kbb = sb + ks * 32;
            unsigned a0[4], a1[4];
            ldsm4(a0, aA[0] + kbb);
            ldsm4(a1, aA[1] + kbb);
#pragma unroll
            for (int p = 0; p < 4; p++) {
                unsigned bb[4];
                ldsm4(bb, aB[p] + kbb);
                mma8(acc[0][2*p],   a0, bb);
                mma8(acc[1][2*p],   a1, bb);
                mma8(acc[0][2*p+1], a0, bb + 2);
                mma8(acc[1][2*p+1], a1, bb + 2);
            }
        }
        __syncthreads();
    }

    int sec = n0 >> 9;
    float* dst = (sec == 0) ? g_Q : (sec == 1 ? g_K : g_V);
    // Q carries 1/sqrt(Dh) * log2(e): softmax becomes pure ex2
    float qs = (sec == 0) ? 0.125f * 1.4426950408889634f : 1.0f;
#pragma unroll
    for (int mt = 0; mt < 2; mt++) {
#pragma unroll
        for (int half = 0; half < 2; half++) {
            int mm = m0 + wm * 32 + mt * 16 + g + half * 8;
            int bb = mm >> 11, ss = mm & (S_ - 1);
#pragma unroll
            for (int nt = 0; nt < 8; nt++) {
                int col = n0 + wn * 64 + nt * 8 + 2 * tg;
                float2 bi = *(const float2*)(bias + col);
                float v0 = tf32f((acc[mt][nt][half * 2 + 0] + bi.x) * qs);
                float v1 = tf32f((acc[mt][nt][half * 2 + 1] + bi.y) * qs);
                int d = col & (D_ - 1);
                int hh = d >> 6, dh = d & 63;
                float* p = dst + (((size_t)(bb * H_ + hh)) * S_ + ss) * DH_ + dh;
                *(float2*)p = make_float2(v0, v1);
            }
        }
    }
}

// ---------------------------------------------------------------------------
// Flash attention: double-buffered K/V, ONE __syncthreads per key tile.
// CTA = 128 q-rows, 128 threads (4 warps x 2 m-frags). LDSM for Q/K/P.
// exp2-domain softmax. V natural layout, scalar B-frags (pitch 72).
// ---------------------------------------------------------------------------
#define QP 68
#define KP 68
#define VP 72
#define KBYTES (64*KP*4)   // 17408 per K buffer
#define VFL    (64*VP)     // floats per V buffer

__global__ __launch_bounds__(128, 2) void attn_kernel() {
    extern __shared__ float sm[];
    float* SP = sm;                    // 128 x 68 : Q, then P
    float* KB = sm + QT_ * QP;         // 2 x (64 x 68)
    float* VB = KB + 2 * 64 * KP;      // 2 x (64 x 72)

    int qt = blockIdx.x, h = blockIdx.y, b = blockIdx.z;
    const float* Qg = g_Q + (((size_t)(b * H_ + h)) * S_ + qt * QT_) * DH_;
    const float* Kg = g_K + ((size_t)(b * H_ + h)) * S_ * DH_;
    const float* Vg = g_V + ((size_t)(b * H_ + h)) * S_ * DH_;

    int tid = threadIdx.x, w = tid >> 5, lane = tid & 31;
    int g = lane >> 2, tg = lane & 3;
    int l8 = lane & 7, b3 = (lane >> 3) & 1, b4 = lane >> 4;
    int r0 = w * 32;                   // warp owns rows [r0, r0+32)

    // LDSM base addresses (K base = buffer 0; add cur*KBYTES at use)
    unsigned aSP[2], aK[4];
#pragma unroll
    for (int f = 0; f < 2; f++)
        aSP[f] = sptr(SP) + ((r0 + f*16 + l8 + b3*8) * QP + b4*4) * 4;
#pragma unroll
    for (int p = 0; p < 4; p++)
        aK[p] = sptr(KB) + (((2*p + b4)*8 + l8) * KP + b3*4) * 4;

    // prologue: Q -> SP (group A) ; K0+V0 -> buffers 0 (group B)
#pragma unroll
    for (int p = 0; p < 16; p++) {
        int slot = tid + p * 128, row = slot >> 4, c4 = (slot & 15) * 4;
        CP16(sptr(&SP[row * QP + c4]), Qg + row * DH_ + c4);
    }
    CPCOMMIT;
#pragma unroll
    for (int p = 0; p < 8; p++) {
        int slot = tid + p * 128, row = slot >> 4, c4 = (slot & 15) * 4;
        CP16(sptr(&KB[row * KP + c4]), Kg + row * DH_ + c4);
        CP16(sptr(&VB[row * VP + c4]), Vg + row * DH_ + c4);
    }
    CPCOMMIT;
    CPWAIT1;          // Q ready (K0/V0 may be in flight)
    __syncthreads();

    // cache Q A-fragments: 2 m-frags x 8 k-steps (LDSM)
    unsigned qf[2][8][4];
#pragma unroll
    for (int f = 0; f < 2; f++)
#pragma unroll
        for (int ks = 0; ks < 8; ks++)
            ldsm4(qf[f][ks], aSP[f] + ks * 32);

    float oacc[2][8][4];
#pragma unroll
    for (int f = 0; f < 2; f++)
#pragma unroll
        for (int dt = 0; dt < 8; dt++)
#pragma unroll
            for (int i = 0; i < 4; i++) oacc[f][dt][i] = 0.f;
    float mrow[2][2], lrow[2][2];
#pragma unroll
    for (int f = 0; f < 2; f++) {
        mrow[f][0] = -CUDART_INF_F; mrow[f][1] = -CUDART_INF_F;
        lrow[f][0] = 0.f; lrow[f][1] = 0.f;
    }

    for (int kt = 0; kt < NT_; kt++) {
        int cur = kt & 1, nxt = cur ^ 1;
        CPWAIT0;              // (K,V)[kt] landed (issued a full iter ago)
        __syncthreads();      // visibility + all warps done with [nxt] buffers

        // prefetch (K,V)[kt+1] into the other buffers — overlaps everything below
        {
            int t1 = (kt + 1) & (NT_ - 1);
            const float* Kt = Kg + (size_t)t1 * 64 * DH_;
            const float* Vt = Vg + (size_t)t1 * 64 * DH_;
#pragma unroll
            for (int p = 0; p < 8; p++) {
                int slot = tid + p * 128, row = slot >> 4, c4 = (slot & 15) * 4;
                CP16(sptr(&KB[nxt * (64*KP) + row * KP + c4]), Kt + row * DH_ + c4);
                CP16(sptr(&VB[nxt * VFL     + row * VP + c4]), Vt + row * DH_ + c4);
            }
            CPCOMMIT;
        }

        // S = Q K^T (KB[cur])
        unsigned kboff = (unsigned)cur * KBYTES;
        float s[2][8][4];
#pragma unroll
        for (int f = 0; f < 2; f++)
#pragma unroll
            for (int nt = 0; nt < 8; nt++)
#pragma unroll
                for (int i = 0; i < 4; i++) s[f][nt][i] = 0.f;
#pragma unroll
        for (int ks = 0; ks < 8; ks++) {
            unsigned kbb = kboff + ks * 32;
#pragma unroll
            for (int p = 0; p < 4; p++) {
                unsigned bb[4];
                ldsm4(bb, aK[p] + kbb);
                mma8(s[0][2*p],   qf[0][ks], bb);
                mma8(s[1][2*p],   qf[1][ks], bb);
                mma8(s[0][2*p+1], qf[0][ks], bb + 2);
                mma8(s[1][2*p+1], qf[1][ks], bb + 2);
            }
        }

        // online softmax (exp2 domain) + P publish (warp-private rows)
#pragma unroll
        for (int f = 0; f < 2; f++) {
            float mxl = -CUDART_INF_F, mxh = -CUDART_INF_F;
#pragma unroll
            for (int nt = 0; nt < 8; nt++) {
                mxl = fmaxf(mxl, fmaxf(s[f][nt][0], s[f][nt][1]));
                mxh = fmaxf(mxh, fmaxf(s[f][nt][2], s[f][nt][3]));
            }
            mxl = fmaxf(mxl, __shfl_xor_sync(0xffffffffu, mxl, 1));
            mxl = fmaxf(mxl, __shfl_xor_sync(0xffffffffu, mxl, 2));
            mxh = fmaxf(mxh, __shfl_xor_sync(0xffffffffu, mxh, 1));
            mxh = fmaxf(mxh, __shfl_xor_sync(0xffffffffu, mxh, 2));
            float mnl = fmaxf(mrow[f][0], mxl), mnh = fmaxf(mrow[f][1], mxh);
            float al = ex2f(mrow[f][0] - mnl), ah = ex2f(mrow[f][1] - mnh);
            mrow[f][0] = mnl; mrow[f][1] = mnh;
            float rsl = 0.f, rsh = 0.f;
#pragma unroll
            for (int nt = 0; nt < 8; nt++) {
                s[f][nt][0] = ex2f(s[f][nt][0] - mnl);
                s[f][nt][1] = ex2f(s[f][nt][1] - mnl);
                s[f][nt][2] = ex2f(s[f][nt][2] - mnh);
                s[f][nt][3] = ex2f(s[f][nt][3] - mnh);
                rsl += s[f][nt][0] + s[f][nt][1];
                rsh += s[f][nt][2] + s[f][nt][3];
            }
            rsl += __shfl_xor_sync(0xffffffffu, rsl, 1);
            rsl += __shfl_xor_sync(0xffffffffu, rsl, 2);
            rsh += __shfl_xor_sync(0xffffffffu, rsh, 1);
            rsh += __shfl_xor_sync(0xffffffffu, rsh, 2);
            lrow[f][0] = lrow[f][0] * al + rsl;
            lrow[f][1] = lrow[f][1] * ah + rsh;
#pragma unroll
            for (int dt = 0; dt < 8; dt++) {
                oacc[f][dt][0] *= al; oacc[f][dt][1] *= al;
                oacc[f][dt][2] *= ah; oacc[f][dt][3] *= ah;
            }
            int rl = r0 + f * 16 + g, rh = rl + 8;
#pragma unroll
            for (int nt = 0; nt < 8; nt++) {
                int c = nt * 8 + 2 * tg;
                *(float2*)&SP[rl * QP + c] = make_float2(tf32f(s[f][nt][0]), tf32f(s[f][nt][1]));
                *(float2*)&SP[rh * QP + c] = make_float2(tf32f(s[f][nt][2]), tf32f(s[f][nt][3]));
            }
        }
        __syncwarp();         // order P stores before P ldmatrix (warp-private)

        // O += P V (VB[cur]) : LDSM P A-frags, scalar V B-frags
        const float* Vc = VB + cur * VFL;
#pragma unroll
        for (int ks = 0; ks < 8; ks++) {
            int kb = ks * 8;
            unsigned pa[2][4];
            ldsm4(pa[0], aSP[0] + ks * 32);
            ldsm4(pa[1], aSP[1] + ks * 32);
#pragma unroll
            for (int dt = 0; dt < 8; dt++) {
                unsigned bb[2];
                bb[0] = fu(Vc[(kb + tg) * VP + dt * 8 + g]);
                bb[1] = fu(Vc[(kb + tg + 4) * VP + dt * 8 + g]);
                mma8(oacc[0][dt], pa[0], bb);
                mma8(oacc[1][dt], pa[1], bb);
            }
        }
        // no trailing barrier: next iter's bar protects buffer reuse
    }

    // epilogue
    float* Og = g_O + ((size_t)(b * S_ + qt * QT_)) * D_ + h * DH_;
#pragma unroll
    for (int f = 0; f < 2; f++) {
        float il = 1.0f / lrow[f][0], ih = 1.0f / lrow[f][1];
        int rl = r0 + f * 16 + g, rh = rl + 8;
#pragma unroll
        for (int dt = 0; dt < 8; dt++) {
            int c = dt * 8 + 2 * tg;
            *(float2*)&Og[(size_t)rl * D_ + c] =
                make_float2(tf32f(oacc[f][dt][0] * il), tf32f(oacc[f][dt][1] * il));
            *(float2*)&Og[(size_t)rh * D_ + c] =
                make_float2(tf32f(oacc[f][dt][2] * ih), tf32f(oacc[f][dt][3] * ih));
        }
    }
}

// ---------------------------------------------------------------------------
// Output projection: g_O[16384,512] @ g_Wo^T + b_out -> out (fp32)
// ---------------------------------------------------------------------------
__global__ __launch_bounds__(256, 2) void out_kernel(const float* __restrict__ bias,
                                                     float* __restrict__ out) {
    extern __shared__ float sm[];
    float* As = sm;
    float* Bs = sm + 2*GST;

    int tid = threadIdx.x;
    int m0 = blockIdx.y * 128, n0 = blockIdx.x * 128;
    int w = tid >> 5, lane = tid & 31;
    int wm = w >> 1, wn = w & 1;
    int g = lane >> 2, tg = lane & 3;
    int lr = tid >> 3, lc4 = (tid & 7) * 4;
    int l8 = lane & 7, b3 = (lane >> 3) & 1, b4 = lane >> 4;

    const float* X = g_O;
    const float* W = g_Wo;

    unsigned aA[2], aB[4];
#pragma unroll
    for (int mt = 0; mt < 2; mt++)
        aA[mt] = sptr(As) + ((wm*32 + mt*16 + l8 + b3*8) * GP + b4*4) * 4;
#pragma unroll
    for (int p = 0; p < 4; p++)
        aB[p] = sptr(Bs) + ((wn*64 + (2*p + b4)*8 + l8) * GP + b3*4) * 4;

#define OUT_ISSUE(kc, stg) do {                                               \
        _Pragma("unroll")                                                     \
        for (int p = 0; p < 4; p++) {                                         \
            int row = lr + p * 32;                                            \
            CP16(sptr(&As[(stg)*GST + row*GP + lc4]),                         \
                 X + (size_t)(m0 + row) * D_ + (kc) + lc4);                   \
            CP16(sptr(&Bs[(stg)*GST + row*GP + lc4]),                         \
                 W + (size_t)(n0 + row) * D_ + (kc) + lc4);                   \
        }                                                                     \
        CPCOMMIT;                                                             \
    } while (0)

    OUT_ISSUE(0, 0);

    float acc[2][8][4];
#pragma unroll
    for (int mt = 0; mt < 2; mt++)
#pragma unroll
        for (int nt = 0; nt < 8; nt++)
#pragma unroll
            for (int i = 0; i < 4; i++) acc[mt][nt][i] = 0.f;

    for (int kci = 0; kci < 16; kci++) {
        int cur = kci & 1;
        if (kci + 1 < 16) { OUT_ISSUE((kci + 1) * 32, cur ^ 1); CPWAIT1; }
        else              { CPWAIT0; }
        __syncthreads();
        unsigned sb = cur * (GST * 4);
#pragma unroll
        for (int ks = 0; ks < 4; ks++) {
            unsigned kbb = sb + ks * 32;
            unsigned a0[4], a1[4];
            ldsm4(a0, aA[0] + kbb);
            ldsm4(a1, aA[1] + kbb);
#pragma unroll
            for (int p = 0; p < 4; p++) {
                unsigned bb[4];
                ldsm4(bb, aB[p] + kbb);
                mma8(acc[0][2*p],   a0, bb);
                mma8(acc[1][2*p],   a1, bb);
                mma8(acc[0][2*p+1], a0, bb + 2);
                mma8(acc[1][2*p+1], a1, bb + 2);
            }
        }
        __syncthreads();
    }

#pragma unroll
    for (int mt = 0; mt < 2; mt++) {
#pragma unroll
        for (int half = 0; half < 2; half++) {
            int mm = m0 + wm * 32 + mt * 16 + g + half * 8;
#pragma unroll
            for (int nt = 0; nt < 8; nt++) {
                int col = n0 + wn * 64 + nt * 8 + 2 * tg;
                float2 bi = *(const float2*)(bias + col);
                *(float2*)&out[(size_t)mm * D_ + col] =
                    make_float2(acc[mt][nt][half * 2 + 0] + bi.x,
                                acc[mt][nt][half * 2 + 1] + bi.y);
            }
        }
    }
}

// ---------------------------------------------------------------------------
extern "C" void kernel_launch(void* const* d_in, const int* in_sizes, int n_in,
                              void* d_out, int out_size) {
    const float* x     = (const float*)d_in[0];
    const float* w_in  = (const float*)d_in[1];
    const float* b_in  = (const float*)d_in[2];
    const float* w_out = (const float*)d_in[3];
    const float* b_out = (const float*)d_in[4];
    float* out = (float*)d_out;

    const int gemm_smem = 4 * GST * 4;                                    // 73728 B
    const int attn_smem = (QT_*QP + 2*64*KP + 2*64*VP) * 4;               // 106496 B
    cudaFuncSetAttribute(qkv_kernel,  cudaFuncAttributeMaxDynamicSharedMemorySize, gemm_smem);
    cudaFuncSetAttribute(out_kernel,  cudaFuncAttributeMaxDynamicSharedMemorySize, gemm_smem);
    cudaFuncSetAttribute(attn_kernel, cudaFuncAttributeMaxDynamicSharedMemorySize, attn_smem);

    float* gx;  cudaGetSymbolAddress((void**)&gx,  g_X);
    float* gwi; cudaGetSymbolAddress((void**)&gwi, g_Wi);
    float* gwo; cudaGetSymbolAddress((void**)&gwo, g_Wo);
    int tot4 = XN4 + WIN4 + WON4;
    round_kernel<<<(tot4 + 255) / 256, 256>>>(
        (const float4*)x, (const float4*)w_in, (const float4*)w_out,
        (float4*)gx, (float4*)gwi, (float4*)gwo);

    qkv_kernel<<<dim3(12, 128), 256, gemm_smem>>>(b_in);
    attn_kernel<<<dim3(S_ / QT_, H_, B_), 128, attn_smem>>>();
    out_kernel<<<dim3(4, 128), 256, gemm_smem>>>(b_out, out);
}

// round 10
// speedup vs baseline: 1.7021x; 1.5636x over previous
#include <cuda_runtime.h>
#include <cuda_fp16.h>
#include <math_constants.h>
#include <cstdint>

#define B_  8
#define S_  2048
#define D_  512
#define H_  8
#define DH_ 64
#define M_  (B_*S_)   // 16384
#define NT_ (S_/64)   // 32 key tiles
#define QT_ 128       // q-rows per attention CTA

// Scratch (allocation-free rule: __device__ globals) — all fp16 now
__device__ __half g_Q[B_*H_*S_*DH_];
__device__ __half g_K[B_*H_*S_*DH_];
__device__ __half g_V[B_*H_*S_*DH_];
__device__ __half g_O[M_*D_];
__device__ __half g_X[M_*D_];
__device__ __half g_Wi[3*D_*D_];
__device__ __half g_Wo[D_*D_];

// ---------------------------------------------------------------------------
// helpers
// ---------------------------------------------------------------------------
__device__ __forceinline__ unsigned h2u(float a, float b) {
    __half2 h = __floats2half2_rn(a, b);
    return *reinterpret_cast<unsigned*>(&h);
}
__device__ __forceinline__ float ex2f(float x) {
    float y;
    asm("ex2.approx.f32 %0, %1;" : "=f"(y) : "f"(x));
    return y;
}

// m16n8k16 fp16 mma, fp32 accumulate
__device__ __forceinline__ void mma16(float* c, const unsigned* a, const unsigned* b) {
    asm volatile(
        "mma.sync.aligned.m16n8k16.row.col.f32.f16.f16.f32 "
        "{%0,%1,%2,%3}, {%4,%5,%6,%7}, {%8,%9}, {%0,%1,%2,%3};"
        : "+f"(c[0]), "+f"(c[1]), "+f"(c[2]), "+f"(c[3])
        : "r"(a[0]), "r"(a[1]), "r"(a[2]), "r"(a[3]), "r"(b[0]), "r"(b[1]));
}

__device__ __forceinline__ void ldsm4(unsigned* r, unsigned addr) {
    asm volatile("ldmatrix.sync.aligned.m8n8.x4.shared.b16 {%0,%1,%2,%3}, [%4];"
                 : "=r"(r[0]), "=r"(r[1]), "=r"(r[2]), "=r"(r[3]) : "r"(addr));
}
__device__ __forceinline__ void ldsm4t(unsigned* r, unsigned addr) {
    asm volatile("ldmatrix.sync.aligned.m8n8.x4.trans.shared.b16 {%0,%1,%2,%3}, [%4];"
                 : "=r"(r[0]), "=r"(r[1]), "=r"(r[2]), "=r"(r[3]) : "r"(addr));
}

__device__ __forceinline__ unsigned sptr(const void* p) {
    return (unsigned)__cvta_generic_to_shared(p);
}
#define CP16(d, s)  asm volatile("cp.async.cg.shared.global [%0], [%1], 16;\n" :: "r"(d), "l"(s))
#define CPCOMMIT    asm volatile("cp.async.commit_group;\n")
#define CPWAIT1     asm volatile("cp.async.wait_group 1;\n")
#define CPWAIT0     asm volatile("cp.async.wait_group 0;\n")

// ---------------------------------------------------------------------------
// fp16 pre-round: all three tensors in one launch (fp32 -> fp16)
// ---------------------------------------------------------------------------
#define XN4  (M_*D_/4)
#define WIN4 (3*D_*D_/4)
#define WON4 (D_*D_/4)

__global__ void round_kernel(const float4* __restrict__ x,
                             const float4* __restrict__ wi,
                             const float4* __restrict__ wo,
                             uint2* __restrict__ gx,
                             uint2* __restrict__ gwi,
                             uint2* __restrict__ gwo) {
    int i = blockIdx.x * 256 + threadIdx.x;
    const float4* src; uint2* dst; int j;
    if (i < XN4)               { src = x;  dst = gx;  j = i; }
    else if (i < XN4 + WIN4)   { src = wi; dst = gwi; j = i - XN4; }
    else if (i < XN4+WIN4+WON4){ src = wo; dst = gwo; j = i - XN4 - WIN4; }
    else return;
    float4 v = src[j];
    dst[j] = make_uint2(h2u(v.x, v.y), h2u(v.z, v.w));
}

// ---------------------------------------------------------------------------
// fp16 GEMM: 128x128 CTA tile, 256 threads (8 warps 4x2), k-chunk 64 halves
// (=128B SW-free rows, pitch 144B), 2-stage cp.async, LDSM frags.
// ---------------------------------------------------------------------------
#define PB  144          // byte pitch (72 halves)
#define STG (128*PB)     // 18432 B per stage tile

// per-thread chunk loader: lr = tid>>1 (row), seg = tid&1 (64B half-row)
#define GISSUE(Xp, Wp, kc, stg) do {                                          \
        const __half* xs = (Xp) + (size_t)(m0 + lr) * D_ + (kc) + seg * 32;   \
        const __half* ws = (Wp) + (size_t)(n0 + lr) * D_ + (kc) + seg * 32;   \
        unsigned da = sptr(As + (stg)*STG + lr*PB + seg*64);                  \
        unsigned db = sptr(Bs + (stg)*STG + lr*PB + seg*64);                  \
        _Pragma("unroll")                                                     \
        for (int u = 0; u < 4; u++) {                                         \
            CP16(da + u*16, xs + u*8);                                        \
            CP16(db + u*16, ws + u*8);                                        \
        }                                                                     \
        CPCOMMIT;                                                             \
    } while (0)

// shared GEMM mainloop body producing acc[2][8][4]
#define GEMM_BODY(Xp, Wp)                                                     \
    unsigned aA[2], aB[4];                                                    \
    _Pragma("unroll")                                                         \
    for (int mt = 0; mt < 2; mt++)                                            \
        aA[mt] = sptr(As) + (wm*32 + mt*16 + l8 + b3*8)*PB + b4*16;           \
    _Pragma("unroll")                                                         \
    for (int p = 0; p < 4; p++)                                               \
        aB[p] = sptr(Bs) + (wn*64 + p*16 + l8 + b4*8)*PB + b3*16;             \
    GISSUE(Xp, Wp, 0, 0);                                                     \
    float acc[2][8][4];                                                       \
    _Pragma("unroll")                                                         \
    for (int mt = 0; mt < 2; mt++)                                            \
        _Pragma("unroll")                                                     \
        for (int nt = 0; nt < 8; nt++)                                        \
            _Pragma("unroll")                                                 \
            for (int i2 = 0; i2 < 4; i2++) acc[mt][nt][i2] = 0.f;             \
    for (int c = 0; c < 8; c++) {                                             \
        int stg = c & 1;                                                      \
        if (c + 1 < 8) { GISSUE(Xp, Wp, (c+1)*64, stg ^ 1); CPWAIT1; }        \
        else           { CPWAIT0; }                                           \
        __syncthreads();                                                      \
        _Pragma("unroll")                                                     \
        for (int ks = 0; ks < 4; ks++) {                                      \
            unsigned off = (unsigned)stg*STG + ks*32;                         \
            unsigned a0[4], a1[4];                                            \
            ldsm4(a0, aA[0] + off);                                           \
            ldsm4(a1, aA[1] + off);                                           \
            _Pragma("unroll")                                                 \
            for (int p = 0; p < 4; p++) {                                     \
                unsigned bb[4];                                               \
                ldsm4(bb, aB[p] + off);                                       \
                mma16(acc[0][2*p],   a0, bb);                                 \
                mma16(acc[1][2*p],   a1, bb);                                 \
                mma16(acc[0][2*p+1], a0, bb + 2);                             \
                mma16(acc[1][2*p+1], a1, bb + 2);                             \
            }                                                                 \
        }                                                                     \
        __syncthreads();                                                      \
    }

// ---------------------------------------------------------------------------
// QKV projection: -> Q,K,V fp16 [B,H,S,Dh]; Q * 0.125*log2(e)
// ---------------------------------------------------------------------------
__global__ __launch_bounds__(256, 2) void qkv_kernel(const float* __restrict__ bias) {
    extern __shared__ char smc[];
    char* As = smc;
    char* Bs = smc + 2*STG;

    int tid = threadIdx.x;
    int m0 = blockIdx.y * 128, n0 = blockIdx.x * 128;
    int w = tid >> 5, lane = tid & 31;
    int wm = w >> 1, wn = w & 1;
    int g = lane >> 2, tg = lane & 3;
    int lr = tid >> 1, seg = tid & 1;
    int l8 = lane & 7, b3 = (lane >> 3) & 1, b4 = lane >> 4;

    GEMM_BODY(g_X, g_Wi)

    int sec = n0 >> 9;
    __half* dst = (sec == 0) ? g_Q : (sec == 1 ? g_K : g_V);
    float qs = (sec == 0) ? 0.125f * 1.4426950408889634f : 1.0f;
#pragma unroll
    for (int mt = 0; mt < 2; mt++) {
#pragma unroll
        for (int hf = 0; hf < 2; hf++) {
            int mm = m0 + wm * 32 + mt * 16 + g + hf * 8;
            int bb = mm >> 11, ss = mm & (S_ - 1);
#pragma unroll
            for (int nt = 0; nt < 8; nt++) {
                int col = n0 + wn * 64 + nt * 8 + 2 * tg;
                float2 bi = *(const float2*)(bias + col);
                float v0 = (acc[mt][nt][hf * 2 + 0] + bi.x) * qs;
                float v1 = (acc[mt][nt][hf * 2 + 1] + bi.y) * qs;
                int d = col & (D_ - 1);
                int hh = d >> 6, dh = d & 63;
                __half* p = dst + (((size_t)(bb * H_ + hh)) * S_ + ss) * DH_ + dh;
                *(unsigned*)p = h2u(v0, v1);
            }
        }
    }
}

// ---------------------------------------------------------------------------
// Output projection: out(fp32) = g_O(fp16) @ g_Wo^T + b_out
// ---------------------------------------------------------------------------
__global__ __launch_bounds__(256, 2) void out_kernel(const float* __restrict__ bias,
                                                     float* __restrict__ out) {
    extern __shared__ char smc[];
    char* As = smc;
    char* Bs = smc + 2*STG;

    int tid = threadIdx.x;
    int m0 = blockIdx.y * 128, n0 = blockIdx.x * 128;
    int w = tid >> 5, lane = tid & 31;
    int wm = w >> 1, wn = w & 1;
    int g = lane >> 2, tg = lane & 3;
    int lr = tid >> 1, seg = tid & 1;
    int l8 = lane & 7, b3 = (lane >> 3) & 1, b4 = lane >> 4;

    GEMM_BODY(g_O, g_Wo)

#pragma unroll
    for (int mt = 0; mt < 2; mt++) {
#pragma unroll
        for (int hf = 0; hf < 2; hf++) {
            int mm = m0 + wm * 32 + mt * 16 + g + hf * 8;
#pragma unroll
            for (int nt = 0; nt < 8; nt++) {
                int col = n0 + wn * 64 + nt * 8 + 2 * tg;
                float2 bi = *(const float2*)(bias + col);
                *(float2*)&out[(size_t)mm * D_ + col] =
                    make_float2(acc[mt][nt][hf * 2 + 0] + bi.x,
                                acc[mt][nt][hf * 2 + 1] + bi.y);
            }
        }
    }
}

// ---------------------------------------------------------------------------
// Flash attention, fp16 mma m16n8k16. Double-buffered K/V, ONE bar per tile.
// All frags via LDSM: Q/K/P non-trans, V trans. exp2-domain softmax.
// Tiles pitch 144 B (72 halves) — ldmatrix conflict-free.
// ---------------------------------------------------------------------------
#define AP  144            // byte pitch
#define KTB (64*AP)        // 9216 B per K or V buffer

__global__ __launch_bounds__(128, 2) void attn_kernel() {
    extern __shared__ char smc[];
    char* SP = smc;                   // 128 rows: Q, then P
    char* KB = smc + 128*AP;          // 2 x 64 rows
    char* VB = KB + 2*KTB;            // 2 x 64 rows

    int qt = blockIdx.x, h = blockIdx.y, b = blockIdx.z;
    const __half* Qg = g_Q + (((size_t)(b * H_ + h)) * S_ + qt * QT_) * DH_;
    const __half* Kg = g_K + ((size_t)(b * H_ + h)) * S_ * DH_;
    const __half* Vg = g_V + ((size_t)(b * H_ + h)) * S_ * DH_;

    int tid = threadIdx.x, w = tid >> 5, lane = tid & 31;
    int g = lane >> 2, tg = lane & 3;
    int l8 = lane & 7, b3 = (lane >> 3) & 1, b4 = lane >> 4;
    int r0 = w * 32;

    // LDSM base addresses
    unsigned aSP[2], aK[4], aV[4];
#pragma unroll
    for (int f = 0; f < 2; f++)
        aSP[f] = sptr(SP) + (r0 + f*16 + l8 + b3*8)*AP + b4*16;
#pragma unroll
    for (int p = 0; p < 4; p++) {
        aK[p] = sptr(KB) + (p*16 + l8 + b4*8)*AP + b3*16;
        aV[p] = sptr(VB) + (l8 + b3*8)*AP + p*32 + b4*16;
    }

    // prologue: Q -> SP ; K0+V0 -> buffers 0
#pragma unroll
    for (int p = 0; p < 8; p++) {
        int slot = tid + p * 128, row = slot >> 3, u = slot & 7;
        CP16(sptr(SP + row*AP + u*16), Qg + row * DH_ + u * 8);
    }
    CPCOMMIT;
#pragma unroll
    for (int p = 0; p < 4; p++) {
        int slot = tid + p * 128, row = slot >> 3, u = slot & 7;
        CP16(sptr(KB + row*AP + u*16), Kg + row * DH_ + u * 8);
        CP16(sptr(VB + row*AP + u*16), Vg + row * DH_ + u * 8);
    }
    CPCOMMIT;
    CPWAIT1;
    __syncthreads();

    // cache Q A-fragments: 2 m-frags x 4 k-steps
    unsigned qf[2][4][4];
#pragma unroll
    for (int f = 0; f < 2; f++)
#pragma unroll
        for (int ks = 0; ks < 4; ks++)
            ldsm4(qf[f][ks], aSP[f] + ks * 32);

    float oacc[2][8][4];
#pragma unroll
    for (int f = 0; f < 2; f++)
#pragma unroll
        for (int dt = 0; dt < 8; dt++)
#pragma unroll
            for (int i = 0; i < 4; i++) oacc[f][dt][i] = 0.f;
    float mrow[2][2], lrow[2][2];
#pragma unroll
    for (int f = 0; f < 2; f++) {
        mrow[f][0] = -CUDART_INF_F; mrow[f][1] = -CUDART_INF_F;
        lrow[f][0] = 0.f; lrow[f][1] = 0.f;
    }

    for (int kt = 0; kt < NT_; kt++) {
        int cur = kt & 1, nxt = cur ^ 1;
        CPWAIT0;
        __syncthreads();

        // prefetch (K,V)[kt+1] — overlaps everything below
        {
            int t1 = (kt + 1) & (NT_ - 1);
            const __half* Kt = Kg + (size_t)t1 * 64 * DH_;
            const __half* Vt = Vg + (size_t)t1 * 64 * DH_;
#pragma unroll
            for (int p = 0; p < 4; p++) {
                int slot = tid + p * 128, row = slot >> 3, u = slot & 7;
                CP16(sptr(KB + nxt*KTB + row*AP + u*16), Kt + row * DH_ + u * 8);
                CP16(sptr(VB + nxt*KTB + row*AP + u*16), Vt + row * DH_ + u * 8);
            }
            CPCOMMIT;
        }

        // S = Q K^T
        float s[2][8][4];
#pragma unroll
        for (int f = 0; f < 2; f++)
#pragma unroll
            for (int nt = 0; nt < 8; nt++)
#pragma unroll
                for (int i = 0; i < 4; i++) s[f][nt][i] = 0.f;
#pragma unroll
        for (int ks = 0; ks < 4; ks++) {
            unsigned off = (unsigned)cur*KTB + ks*32;
#pragma unroll
            for (int p = 0; p < 4; p++) {
                unsigned bb[4];
                ldsm4(bb, aK[p] + off);
                mma16(s[0][2*p],   qf[0][ks], bb);
                mma16(s[1][2*p],   qf[1][ks], bb);
                mma16(s[0][2*p+1], qf[0][ks], bb + 2);
                mma16(s[1][2*p+1], qf[1][ks], bb + 2);
            }
        }

        // online softmax (exp2 domain) + P publish (fp16, warp-private rows)
#pragma unroll
        for (int f = 0; f < 2; f++) {
            float mxl = -CUDART_INF_F, mxh = -CUDART_INF_F;
#pragma unroll
            for (int nt = 0; nt < 8; nt++) {
                mxl = fmaxf(mxl, fmaxf(s[f][nt][0], s[f][nt][1]));
                mxh = fmaxf(mxh, fmaxf(s[f][nt][2], s[f][nt][3]));
            }
            mxl = fmaxf(mxl, __shfl_xor_sync(0xffffffffu, mxl, 1));
            mxl = fmaxf(mxl, __shfl_xor_sync(0xffffffffu, mxl, 2));
            mxh = fmaxf(mxh, __shfl_xor_sync(0xffffffffu, mxh, 1));
            mxh = fmaxf(mxh, __shfl_xor_sync(0xffffffffu, mxh, 2));
            float mnl = fmaxf(mrow[f][0], mxl), mnh = fmaxf(mrow[f][1], mxh);
            float al = ex2f(mrow[f][0] - mnl), ah = ex2f(mrow[f][1] - mnh);
            mrow[f][0] = mnl; mrow[f][1] = mnh;
            float rsl = 0.f, rsh = 0.f;
#pragma unroll
            for (int nt = 0; nt < 8; nt++) {
                s[f][nt][0] = ex2f(s[f][nt][0] - mnl);
                s[f][nt][1] = ex2f(s[f][nt][1] - mnl);
                s[f][nt][2] = ex2f(s[f][nt][2] - mnh);
                s[f][nt][3] = ex2f(s[f][nt][3] - mnh);
                rsl += s[f][nt][0] + s[f][nt][1];
                rsh += s[f][nt][2] + s[f][nt][3];
            }
            rsl += __shfl_xor_sync(0xffffffffu, rsl, 1);
            rsl += __shfl_xor_sync(0xffffffffu, rsl, 2);
            rsh += __shfl_xor_sync(0xffffffffu, rsh, 1);
            rsh += __shfl_xor_sync(0xffffffffu, rsh, 2);
            lrow[f][0] = lrow[f][0] * al + rsl;
            lrow[f][1] = lrow[f][1] * ah + rsh;
#pragma unroll
            for (int dt = 0; dt < 8; dt++) {
                oacc[f][dt][0] *= al; oacc[f][dt][1] *= al;
                oacc[f][dt][2] *= ah; oacc[f][dt][3] *= ah;
            }
            int rl = r0 + f * 16 + g, rh = rl + 8;
#pragma unroll
            for (int nt = 0; nt < 8; nt++) {
                *(unsigned*)(SP + rl*AP + nt*16 + tg*4) = h2u(s[f][nt][0], s[f][nt][1]);
                *(unsigned*)(SP + rh*AP + nt*16 + tg*4) = h2u(s[f][nt][2], s[f][nt][3]);
            }
        }
        __syncwarp();      // order P stores before P ldmatrix (warp-private)

        // O += P V : LDSM P A-frags (non-trans), V B-frags (trans)
#pragma unroll
        for (int ks = 0; ks < 4; ks++) {
            unsigned pa[2][4];
            ldsm4(pa[0], aSP[0] + ks * 32);
            ldsm4(pa[1], aSP[1] + ks * 32);
            unsigned voff = (unsigned)cur*KTB + ks*16*AP;
#pragma unroll
            for (int p = 0; p < 4; p++) {
                unsigned vb[4];
                ldsm4t(vb, aV[p] + voff);
                mma16(oacc[0][2*p],   pa[0], vb);
                mma16(oacc[1][2*p],   pa[1], vb);
                mma16(oacc[0][2*p+1], pa[0], vb + 2);
                mma16(oacc[1][2*p+1], pa[1], vb + 2);
            }
        }
        // no trailing barrier: next iteration's bar protects buffer reuse
    }

    // epilogue: normalize, convert fp16, write g_O (B, S, H*Dh)
    __half* Og = g_O + ((size_t)(b * S_ + qt * QT_)) * D_ + h * DH_;
#pragma unroll
    for (int f = 0; f < 2; f++) {
        float il = 1.0f / lrow[f][0], ih = 1.0f / lrow[f][1];
        int rl = r0 + f * 16 + g, rh = rl + 8;
#pragma unroll
        for (int dt = 0; dt < 8; dt++) {
            int c = dt * 8 + 2 * tg;
            *(unsigned*)&Og[(size_t)rl * D_ + c] = h2u(oacc[f][dt][0] * il, oacc[f][dt][1] * il);
            *(unsigned*)&Og[(size_t)rh * D_ + c] = h2u(oacc[f][dt][2] * ih, oacc[f][dt][3] * ih);
        }
    }
}

// ---------------------------------------------------------------------------
extern "C" void kernel_launch(void* const* d_in, const int* in_sizes, int n_in,
                              void* d_out, int out_size) {
    const float* x     = (const float*)d_in[0];
    const float* w_in  = (const float*)d_in[1];
    const float* b_in  = (const float*)d_in[2];
    const float* w_out = (const float*)d_in[3];
    const float* b_out = (const float*)d_in[4];
    float* out = (float*)d_out;

    const int gemm_smem = 4 * STG;                    // 73728 B
    const int attn_smem = 128*AP + 4*KTB;             // 55296 B
    cudaFuncSetAttribute(qkv_kernel,  cudaFuncAttributeMaxDynamicSharedMemorySize, gemm_smem);
    cudaFuncSetAttribute(out_kernel,  cudaFuncAttributeMaxDynamicSharedMemorySize, gemm_smem);
    cudaFuncSetAttribute(attn_kernel, cudaFuncAttributeMaxDynamicSharedMemorySize, attn_smem);

    __half* gx;  cudaGetSymbolAddress((void**)&gx,  g_X);
    __half* gwi; cudaGetSymbolAddress((void**)&gwi, g_Wi);
    __half* gwo; cudaGetSymbolAddress((void**)&gwo, g_Wo);
    int tot4 = XN4 + WIN4 + WON4;
    round_kernel<<<(tot4 + 255) / 256, 256>>>(
        (const float4*)x, (const float4*)w_in, (const float4*)w_out,
        (uint2*)gx, (uint2*)gwi, (uint2*)gwo);

    qkv_kernel<<<dim3(12, 128), 256, gemm_smem>>>(b_in);
    attn_kernel<<<dim3(S_ / QT_, H_, B_), 128, attn_smem>>>();
    out_kernel<<<dim3(4, 128), 256, gemm_smem>>>(b_out, out);
}

// round 11
// speedup vs baseline: 1.7865x; 1.0496x over previous
#include <cuda_runtime.h>
#include <cuda_fp16.h>
#include <math_constants.h>
#include <cstdint>

#define B_  8
#define S_  2048
#define D_  512
#define H_  8
#define DH_ 64
#define M_  (B_*S_)   // 16384
#define NT_ (S_/64)   // 32 key tiles
#define QT_ 128       // q-rows per attention CTA

// Scratch (allocation-free rule: __device__ globals) — all fp16
__device__ __half g_Q[B_*H_*S_*DH_];
__device__ __half g_K[B_*H_*S_*DH_];
__device__ __half g_V[B_*H_*S_*DH_];
__device__ __half g_O[M_*D_];
__device__ __half g_X[M_*D_];
__device__ __half g_Wi[3*D_*D_];
__device__ __half g_Wo[D_*D_];

// ---------------------------------------------------------------------------
// helpers
// ---------------------------------------------------------------------------
__device__ __forceinline__ unsigned h2u(float a, float b) {
    __half2 h = __floats2half2_rn(a, b);
    return *reinterpret_cast<unsigned*>(&h);
}
__device__ __forceinline__ float ex2f(float x) {
    float y;
    asm("ex2.approx.f32 %0, %1;" : "=f"(y) : "f"(x));
    return y;
}

// m16n8k16 fp16 mma, fp32 accumulate
__device__ __forceinline__ void mma16(float* c, const unsigned* a, const unsigned* b) {
    asm volatile(
        "mma.sync.aligned.m16n8k16.row.col.f32.f16.f16.f32 "
        "{%0,%1,%2,%3}, {%4,%5,%6,%7}, {%8,%9}, {%0,%1,%2,%3};"
        : "+f"(c[0]), "+f"(c[1]), "+f"(c[2]), "+f"(c[3])
        : "r"(a[0]), "r"(a[1]), "r"(a[2]), "r"(a[3]), "r"(b[0]), "r"(b[1]));
}

__device__ __forceinline__ void ldsm4(unsigned* r, unsigned addr) {
    asm volatile("ldmatrix.sync.aligned.m8n8.x4.shared.b16 {%0,%1,%2,%3}, [%4];"
                 : "=r"(r[0]), "=r"(r[1]), "=r"(r[2]), "=r"(r[3]) : "r"(addr));
}
__device__ __forceinline__ void ldsm4t(unsigned* r, unsigned addr) {
    asm volatile("ldmatrix.sync.aligned.m8n8.x4.trans.shared.b16 {%0,%1,%2,%3}, [%4];"
                 : "=r"(r[0]), "=r"(r[1]), "=r"(r[2]), "=r"(r[3]) : "r"(addr));
}

__device__ __forceinline__ unsigned sptr(const void* p) {
    return (unsigned)__cvta_generic_to_shared(p);
}
#define CP16(d, s)  asm volatile("cp.async.cg.shared.global [%0], [%1], 16;\n" :: "r"(d), "l"(s))
#define CPCOMMIT    asm volatile("cp.async.commit_group;\n")
#define CPWAIT1     asm volatile("cp.async.wait_group 1;\n")
#define CPWAIT0     asm volatile("cp.async.wait_group 0;\n")

// ---------------------------------------------------------------------------
// fp16 pre-round: all three tensors in one launch (fp32 -> fp16)
// ---------------------------------------------------------------------------
#define XN4  (M_*D_/4)
#define WIN4 (3*D_*D_/4)
#define WON4 (D_*D_/4)

__global__ void round_kernel(const float4* __restrict__ x,
                             const float4* __restrict__ wi,
                             const float4* __restrict__ wo,
                             uint2* __restrict__ gx,
                             uint2* __restrict__ gwi,
                             uint2* __restrict__ gwo) {
    int i = blockIdx.x * 256 + threadIdx.x;
    const float4* src; uint2* dst; int j;
    if (i < XN4)               { src = x;  dst = gx;  j = i; }
    else if (i < XN4 + WIN4)   { src = wi; dst = gwi; j = i - XN4; }
    else if (i < XN4+WIN4+WON4){ src = wo; dst = gwo; j = i - XN4 - WIN4; }
    else return;
    float4 v = src[j];
    dst[j] = make_uint2(h2u(v.x, v.y), h2u(v.z, v.w));
}

// ---------------------------------------------------------------------------
// fp16 GEMM: 128x128 CTA tile, 256 threads (8 warps 4x2), k-chunk 64 halves
// (=128B rows, pitch 144B), 2-stage cp.async, LDSM frags.
// ---------------------------------------------------------------------------
#define PB  144          // byte pitch (72 halves)
#define STG (128*PB)     // 18432 B per stage tile

#define GISSUE(Xp, Wp, kc, stg) do {                                          \
        const __half* xs = (Xp) + (size_t)(m0 + lr) * D_ + (kc) + seg * 32;   \
        const __half* ws = (Wp) + (size_t)(n0 + lr) * D_ + (kc) + seg * 32;   \
        unsigned da = sptr(As + (stg)*STG + lr*PB + seg*64);                  \
        unsigned db = sptr(Bs + (stg)*STG + lr*PB + seg*64);                  \
        _Pragma("unroll")                                                     \
        for (int u = 0; u < 4; u++) {                                         \
            CP16(da + u*16, xs + u*8);                                        \
            CP16(db + u*16, ws + u*8);                                        \
        }                                                                     \
        CPCOMMIT;                                                             \
    } while (0)

#define GEMM_BODY(Xp, Wp)                                                     \
    unsigned aA[2], aB[4];                                                    \
    _Pragma("unroll")                                                         \
    for (int mt = 0; mt < 2; mt++)                                            \
        aA[mt] = sptr(As) + (wm*32 + mt*16 + l8 + b3*8)*PB + b4*16;           \
    _Pragma("unroll")                                                         \
    for (int p = 0; p < 4; p++)                                               \
        aB[p] = sptr(Bs) + (wn*64 + p*16 + l8 + b4*8)*PB + b3*16;             \
    GISSUE(Xp, Wp, 0, 0);                                                     \
    float acc[2][8][4];                                                       \
    _Pragma("unroll")                                                         \
    for (int mt = 0; mt < 2; mt++)                                            \
        _Pragma("unroll")                                                     \
        for (int nt = 0; nt < 8; nt++)                                        \
            _Pragma("unroll")                                                 \
            for (int i2 = 0; i2 < 4; i2++) acc[mt][nt][i2] = 0.f;             \
    for (int c = 0; c < 8; c++) {                                             \
        int stg = c & 1;                                                      \
        if (c + 1 < 8) { GISSUE(Xp, Wp, (c+1)*64, stg ^ 1); CPWAIT1; }        \
        else           { CPWAIT0; }                                           \
        __syncthreads();                                                      \
        _Pragma("unroll")                                                     \
        for (int ks = 0; ks < 4; ks++) {                                      \
            unsigned off = (unsigned)stg*STG + ks*32;                         \
            unsigned a0[4], a1[4];                                            \
            ldsm4(a0, aA[0] + off);                                           \
            ldsm4(a1, aA[1] + off);                                           \
            _Pragma("unroll")                                                 \
            for (int p = 0; p < 4; p++) {                                     \
                unsigned bb[4];                                               \
                ldsm4(bb, aB[p] + off);                                       \
                mma16(acc[0][2*p],   a0, bb);                                 \
                mma16(acc[1][2*p],   a1, bb);                                 \
                mma16(acc[0][2*p+1], a0, bb + 2);                             \
                mma16(acc[1][2*p+1], a1, bb + 2);                             \
            }                                                                 \
        }                                                                     \
        __syncthreads();                                                      \
    }

// ---------------------------------------------------------------------------
// QKV projection: -> Q,K,V fp16 [B,H,S,Dh]; Q * 0.125*log2(e)
// ---------------------------------------------------------------------------
__global__ __launch_bounds__(256, 2) void qkv_kernel(const float* __restrict__ bias) {
    extern __shared__ char smc[];
    char* As = smc;
    char* Bs = smc + 2*STG;

    int tid = threadIdx.x;
    int m0 = blockIdx.y * 128, n0 = blockIdx.x * 128;
    int w = tid >> 5, lane = tid & 31;
    int wm = w >> 1, wn = w & 1;
    int g = lane >> 2, tg = lane & 3;
    int lr = tid >> 1, seg = tid & 1;
    int l8 = lane & 7, b3 = (lane >> 3) & 1, b4 = lane >> 4;

    GEMM_BODY(g_X, g_Wi)

    int sec = n0 >> 9;
    __half* dst = (sec == 0) ? g_Q : (sec == 1 ? g_K : g_V);
    float qs = (sec == 0) ? 0.125f * 1.4426950408889634f : 1.0f;
#pragma unroll
    for (int mt = 0; mt < 2; mt++) {
#pragma unroll
        for (int hf = 0; hf < 2; hf++) {
            int mm = m0 + wm * 32 + mt * 16 + g + hf * 8;
            int bb = mm >> 11, ss = mm & (S_ - 1);
#pragma unroll
            for (int nt = 0; nt < 8; nt++) {
                int col = n0 + wn * 64 + nt * 8 + 2 * tg;
                float2 bi = *(const float2*)(bias + col);
                float v0 = (acc[mt][nt][hf * 2 + 0] + bi.x) * qs;
                float v1 = (acc[mt][nt][hf * 2 + 1] + bi.y) * qs;
                int d = col & (D_ - 1);
                int hh = d >> 6, dh = d & 63;
                __half* p = dst + (((size_t)(bb * H_ + hh)) * S_ + ss) * DH_ + dh;
                *(unsigned*)p = h2u(v0, v1);
            }
        }
    }
}

// ---------------------------------------------------------------------------
// Output projection: out(fp32) = g_O(fp16) @ g_Wo^T + b_out
// ---------------------------------------------------------------------------
__global__ __launch_bounds__(256, 2) void out_kernel(const float* __restrict__ bias,
                                                     float* __restrict__ out) {
    extern __shared__ char smc[];
    char* As = smc;
    char* Bs = smc + 2*STG;

    int tid = threadIdx.x;
    int m0 = blockIdx.y * 128, n0 = blockIdx.x * 128;
    int w = tid >> 5, lane = tid & 31;
    int wm = w >> 1, wn = w & 1;
    int g = lane >> 2, tg = lane & 3;
    int lr = tid >> 1, seg = tid & 1;
    int l8 = lane & 7, b3 = (lane >> 3) & 1, b4 = lane >> 4;

    GEMM_BODY(g_O, g_Wo)

#pragma unroll
    for (int mt = 0; mt < 2; mt++) {
#pragma unroll
        for (int hf = 0; hf < 2; hf++) {
            int mm = m0 + wm * 32 + mt * 16 + g + hf * 8;
#pragma unroll
            for (int nt = 0; nt < 8; nt++) {
                int col = n0 + wn * 64 + nt * 8 + 2 * tg;
                float2 bi = *(const float2*)(bias + col);
                *(float2*)&out[(size_t)mm * D_ + col] =
                    make_float2(acc[mt][nt][hf * 2 + 0] + bi.x,
                                acc[mt][nt][hf * 2 + 1] + bi.y);
            }
        }
    }
}

// ---------------------------------------------------------------------------
// Flash attention, fp16 mma. Double-buffered K/V, ONE bar per tile.
// P stays ENTIRELY in registers: the S-accumulator fragment layout equals
// the PV A-fragment layout (c0c1/c2c3 of S n-tiles 2ks,2ks+1 == a0..a3 of
// PV k-block ks), so h2u-packed accumulators feed mma directly.
// ---------------------------------------------------------------------------
#define AP  144            // byte pitch
#define KTB (64*AP)        // 9216 B per K or V buffer

__global__ __launch_bounds__(128, 2) void attn_kernel() {
    extern __shared__ char smc[];
    char* SP = smc;                   // 128 rows: Q (prologue only)
    char* KB = smc + 128*AP;          // 2 x 64 rows
    char* VB = KB + 2*KTB;            // 2 x 64 rows

    int qt = blockIdx.x, h = blockIdx.y, b = blockIdx.z;
    const __half* Qg = g_Q + (((size_t)(b * H_ + h)) * S_ + qt * QT_) * DH_;
    const __half* Kg = g_K + ((size_t)(b * H_ + h)) * S_ * DH_;
    const __half* Vg = g_V + ((size_t)(b * H_ + h)) * S_ * DH_;

    int tid = threadIdx.x, w = tid >> 5, lane = tid & 31;
    int g = lane >> 2, tg = lane & 3;
    int l8 = lane & 7, b3 = (lane >> 3) & 1, b4 = lane >> 4;
    int r0 = w * 32;

    // LDSM base addresses
    unsigned aSP[2], aK[4], aV[4];
#pragma unroll
    for (int f = 0; f < 2; f++)
        aSP[f] = sptr(SP) + (r0 + f*16 + l8 + b3*8)*AP + b4*16;
#pragma unroll
    for (int p = 0; p < 4; p++) {
        aK[p] = sptr(KB) + (p*16 + l8 + b4*8)*AP + b3*16;
        aV[p] = sptr(VB) + (l8 + b3*8)*AP + p*32 + b4*16;
    }

    // prologue: Q -> SP ; K0+V0 -> buffers 0
#pragma unroll
    for (int p = 0; p < 8; p++) {
        int slot = tid + p * 128, row = slot >> 3, u = slot & 7;
        CP16(sptr(SP + row*AP + u*16), Qg + row * DH_ + u * 8);
    }
    CPCOMMIT;
#pragma unroll
    for (int p = 0; p < 4; p++) {
        int slot = tid + p * 128, row = slot >> 3, u = slot & 7;
        CP16(sptr(KB + row*AP + u*16), Kg + row * DH_ + u * 8);
        CP16(sptr(VB + row*AP + u*16), Vg + row * DH_ + u * 8);
    }
    CPCOMMIT;
    CPWAIT1;
    __syncthreads();

    // cache Q A-fragments: 2 m-frags x 4 k-steps
    unsigned qf[2][4][4];
#pragma unroll
    for (int f = 0; f < 2; f++)
#pragma unroll
        for (int ks = 0; ks < 4; ks++)
            ldsm4(qf[f][ks], aSP[f] + ks * 32);

    float oacc[2][8][4];
#pragma unroll
    for (int f = 0; f < 2; f++)
#pragma unroll
        for (int dt = 0; dt < 8; dt++)
#pragma unroll
            for (int i = 0; i < 4; i++) oacc[f][dt][i] = 0.f;
    float mrow[2][2], lrow[2][2];
#pragma unroll
    for (int f = 0; f < 2; f++) {
        mrow[f][0] = -CUDART_INF_F; mrow[f][1] = -CUDART_INF_F;
        lrow[f][0] = 0.f; lrow[f][1] = 0.f;
    }

    for (int kt = 0; kt < NT_; kt++) {
        int cur = kt & 1, nxt = cur ^ 1;
        CPWAIT0;
        __syncthreads();

        // prefetch (K,V)[kt+1] — overlaps everything below
        {
            int t1 = (kt + 1) & (NT_ - 1);
            const __half* Kt = Kg + (size_t)t1 * 64 * DH_;
            const __half* Vt = Vg + (size_t)t1 * 64 * DH_;
#pragma unroll
            for (int p = 0; p < 4; p++) {
                int slot = tid + p * 128, row = slot >> 3, u = slot & 7;
                CP16(sptr(KB + nxt*KTB + row*AP + u*16), Kt + row * DH_ + u * 8);
                CP16(sptr(VB + nxt*KTB + row*AP + u*16), Vt + row * DH_ + u * 8);
            }
            CPCOMMIT;
        }

        // S = Q K^T
        float s[2][8][4];
#pragma unroll
        for (int f = 0; f < 2; f++)
#pragma unroll
            for (int nt = 0; nt < 8; nt++)
#pragma unroll
                for (int i = 0; i < 4; i++) s[f][nt][i] = 0.f;
#pragma unroll
        for (int ks = 0; ks < 4; ks++) {
            unsigned off = (unsigned)cur*KTB + ks*32;
#pragma unroll
            for (int p = 0; p < 4; p++) {
                unsigned bb[4];
                ldsm4(bb, aK[p] + off);
                mma16(s[0][2*p],   qf[0][ks], bb);
                mma16(s[1][2*p],   qf[1][ks], bb);
                mma16(s[0][2*p+1], qf[0][ks], bb + 2);
                mma16(s[1][2*p+1], qf[1][ks], bb + 2);
            }
        }

        // online softmax (exp2 domain) — P stays in registers
#pragma unroll
        for (int f = 0; f < 2; f++) {
            float mxl = -CUDART_INF_F, mxh = -CUDART_INF_F;
#pragma unroll
            for (int nt = 0; nt < 8; nt++) {
                mxl = fmaxf(mxl, fmaxf(s[f][nt][0], s[f][nt][1]));
                mxh = fmaxf(mxh, fmaxf(s[f][nt][2], s[f][nt][3]));
            }
            mxl = fmaxf(mxl, __shfl_xor_sync(0xffffffffu, mxl, 1));
            mxl = fmaxf(mxl, __shfl_xor_sync(0xffffffffu, mxl, 2));
            mxh = fmaxf(mxh, __shfl_xor_sync(0xffffffffu, mxh, 1));
            mxh = fmaxf(mxh, __shfl_xor_sync(0xffffffffu, mxh, 2));
            float mnl = fmaxf(mrow[f][0], mxl), mnh = fmaxf(mrow[f][1], mxh);
            float al = ex2f(mrow[f][0] - mnl), ah = ex2f(mrow[f][1] - mnh);
            mrow[f][0] = mnl; mrow[f][1] = mnh;
            float rsl = 0.f, rsh = 0.f;
#pragma unroll
            for (int nt = 0; nt < 8; nt++) {
                s[f][nt][0] = ex2f(s[f][nt][0] - mnl);
                s[f][nt][1] = ex2f(s[f][nt][1] - mnl);
                s[f][nt][2] = ex2f(s[f][nt][2] - mnh);
                s[f][nt][3] = ex2f(s[f][nt][3] - mnh);
                rsl += s[f][nt][0] + s[f][nt][1];
                rsh += s[f][nt][2] + s[f][nt][3];
            }
            rsl += __shfl_xor_sync(0xffffffffu, rsl, 1);
            rsl += __shfl_xor_sync(0xffffffffu, rsl, 2);
            rsh += __shfl_xor_sync(0xffffffffu, rsh, 1);
            rsh += __shfl_xor_sync(0xffffffffu, rsh, 2);
            lrow[f][0] = lrow[f][0] * al + rsl;
            lrow[f][1] = lrow[f][1] * ah + rsh;
#pragma unroll
            for (int dt = 0; dt < 8; dt++) {
                oacc[f][dt][0] *= al; oacc[f][dt][1] *= al;
                oacc[f][dt][2] *= ah; oacc[f][dt][3] *= ah;
            }
        }

        // O += P V : P A-frags built in-register from S accumulators;
        // V B-frags via ldmatrix.trans
#pragma unroll
        for (int ks = 0; ks < 4; ks++) {
            unsigned pa[2][4];
#pragma unroll
            for (int f = 0; f < 2; f++) {
                pa[f][0] = h2u(s[f][2*ks][0],   s[f][2*ks][1]);
                pa[f][1] = h2u(s[f][2*ks][2],   s[f][2*ks][3]);
                pa[f][2] = h2u(s[f][2*ks+1][0], s[f][2*ks+1][1]);
                pa[f][3] = h2u(s[f][2*ks+1][2], s[f][2*ks+1][3]);
            }
            unsigned voff = (unsigned)cur*KTB + ks*16*AP;
#pragma unroll
            for (int p = 0; p < 4; p++) {
                unsigned vb[4];
                ldsm4t(vb, aV[p] + voff);
                mma16(oacc[0][2*p],   pa[0], vb);
                mma16(oacc[1][2*p],   pa[1], vb);
                mma16(oacc[0][2*p+1], pa[0], vb + 2);
                mma16(oacc[1][2*p+1], pa[1], vb + 2);
            }
        }
        // no trailing barrier: next iteration's bar protects buffer reuse
    }

    // epilogue: normalize, convert fp16, write g_O (B, S, H*Dh)
    __half* Og = g_O + ((size_t)(b * S_ + qt * QT_)) * D_ + h * DH_;
#pragma unroll
    for (int f = 0; f < 2; f++) {
        float il = 1.0f / lrow[f][0], ih = 1.0f / lrow[f][1];
        int rl = r0 + f * 16 + g, rh = rl + 8;
#pragma unroll
        for (int dt = 0; dt < 8; dt++) {
            int c = dt * 8 + 2 * tg;
            *(unsigned*)&Og[(size_t)rl * D_ + c] = h2u(oacc[f][dt][0] * il, oacc[f][dt][1] * il);
            *(unsigned*)&Og[(size_t)rh * D_ + c] = h2u(oacc[f][dt][2] * ih, oacc[f][dt][3] * ih);
        }
    }
}

// ---------------------------------------------------------------------------
extern "C" void kernel_launch(void* const* d_in, const int* in_sizes, int n_in,
                              void* d_out, int out_size) {
    const float* x     = (const float*)d_in[0];
    const float* w_in  = (const float*)d_in[1];
    const float* b_in  = (const float*)d_in[2];
    const float* w_out = (const float*)d_in[3];
    const float* b_out = (const float*)d_in[4];
    float* out = (float*)d_out;

    const int gemm_smem = 4 * STG;                    // 73728 B
    const int attn_smem = 128*AP + 4*KTB;             // 55296 B
    cudaFuncSetAttribute(qkv_kernel,  cudaFuncAttributeMaxDynamicSharedMemorySize, gemm_smem);
    cudaFuncSetAttribute(out_kernel,  cudaFuncAttributeMaxDynamicSharedMemorySize, gemm_smem);
    cudaFuncSetAttribute(attn_kernel, cudaFuncAttributeMaxDynamicSharedMemorySize, attn_smem);

    __half* gx;  cudaGetSymbolAddress((void**)&gx,  g_X);
    __half* gwi; cudaGetSymbolAddress((void**)&gwi, g_Wi);
    __half* gwo; cudaGetSymbolAddress((void**)&gwo, g_Wo);
    int tot4 = XN4 + WIN4 + WON4;
    round_kernel<<<(tot4 + 255) / 256, 256>>>(
        (const float4*)x, (const float4*)w_in, (const float4*)w_out,
        (uint2*)gx, (uint2*)gwi, (uint2*)gwo);

    qkv_kernel<<<dim3(12, 128), 256, gemm_smem>>>(b_in);
    attn_kernel<<<dim3(S_ / QT_, H_, B_), 128, attn_smem>>>();
    out_kernel<<<dim3(4, 128), 256, gemm_smem>>>(b_out, out);
}

// round 12
// speedup vs baseline: 1.8473x; 1.0340x over previous
#include <cuda_runtime.h>
#include <cuda_fp16.h>
#include <math_constants.h>
#include <cstdint>

#define B_  8
#define S_  2048
#define D_  512
#define H_  8
#define DH_ 64
#define M_  (B_*S_)   // 16384
#define NT_ (S_/64)   // 32 key tiles
#define QT_ 128       // q-rows per attention CTA

// Scratch (allocation-free rule: __device__ globals) — all fp16
__device__ __half g_Q[B_*H_*S_*DH_];
__device__ __half g_K[B_*H_*S_*DH_];
__device__ __half g_V[B_*H_*S_*DH_];
__device__ __half g_O[M_*D_];
__device__ __half g_X[M_*D_];
__device__ __half g_Wi[3*D_*D_];
__device__ __half g_Wo[D_*D_];

// ---------------------------------------------------------------------------
// helpers
// ---------------------------------------------------------------------------
__device__ __forceinline__ unsigned h2u(float a, float b) {
    __half2 h = __floats2half2_rn(a, b);
    return *reinterpret_cast<unsigned*>(&h);
}
__device__ __forceinline__ float ex2f(float x) {
    float y;
    asm("ex2.approx.f32 %0, %1;" : "=f"(y) : "f"(x));
    return y;
}

// m16n8k16 fp16 mma, fp32 accumulate
__device__ __forceinline__ void mma16(float* c, const unsigned* a, const unsigned* b) {
    asm volatile(
        "mma.sync.aligned.m16n8k16.row.col.f32.f16.f16.f32 "
        "{%0,%1,%2,%3}, {%4,%5,%6,%7}, {%8,%9}, {%0,%1,%2,%3};"
        : "+f"(c[0]), "+f"(c[1]), "+f"(c[2]), "+f"(c[3])
        : "r"(a[0]), "r"(a[1]), "r"(a[2]), "r"(a[3]), "r"(b[0]), "r"(b[1]));
}

__device__ __forceinline__ void ldsm4(unsigned* r, unsigned addr) {
    asm volatile("ldmatrix.sync.aligned.m8n8.x4.shared.b16 {%0,%1,%2,%3}, [%4];"
                 : "=r"(r[0]), "=r"(r[1]), "=r"(r[2]), "=r"(r[3]) : "r"(addr));
}
__device__ __forceinline__ void ldsm4t(unsigned* r, unsigned addr) {
    asm volatile("ldmatrix.sync.aligned.m8n8.x4.trans.shared.b16 {%0,%1,%2,%3}, [%4];"
                 : "=r"(r[0]), "=r"(r[1]), "=r"(r[2]), "=r"(r[3]) : "r"(addr));
}

__device__ __forceinline__ unsigned sptr(const void* p) {
    return (unsigned)__cvta_generic_to_shared(p);
}
#define CP16(d, s)  asm volatile("cp.async.cg.shared.global [%0], [%1], 16;\n" :: "r"(d), "l"(s))
#define CPCOMMIT    asm volatile("cp.async.commit_group;\n")
#define CPWAIT1     asm volatile("cp.async.wait_group 1;\n")
#define CPWAIT0     asm volatile("cp.async.wait_group 0;\n")

// ---------------------------------------------------------------------------
// fp16 pre-round: all three tensors in one launch (fp32 -> fp16)
// ---------------------------------------------------------------------------
#define XN4  (M_*D_/4)
#define WIN4 (3*D_*D_/4)
#define WON4 (D_*D_/4)

__global__ void round_kernel(const float4* __restrict__ x,
                             const float4* __restrict__ wi,
                             const float4* __restrict__ wo,
                             uint2* __restrict__ gx,
                             uint2* __restrict__ gwi,
                             uint2* __restrict__ gwo) {
    int i = blockIdx.x * 256 + threadIdx.x;
    const float4* src; uint2* dst; int j;
    if (i < XN4)               { src = x;  dst = gx;  j = i; }
    else if (i < XN4 + WIN4)   { src = wi; dst = gwi; j = i - XN4; }
    else if (i < XN4+WIN4+WON4){ src = wo; dst = gwo; j = i - XN4 - WIN4; }
    else return;
    float4 v = src[j];
    dst[j] = make_uint2(h2u(v.x, v.y), h2u(v.z, v.w));
}

// ---------------------------------------------------------------------------
// fp16 GEMM: 128x128 CTA tile, 256 threads (8 warps 4x2), k-chunk 64 halves
// (=128B rows, pitch 144B), double-buffered cp.async, ONE barrier per chunk.
// ---------------------------------------------------------------------------
#define PB  144          // byte pitch (72 halves)
#define STG (128*PB)     // 18432 B per stage tile

#define GISSUE(Xp, Wp, kc, stg) do {                                          \
        const __half* xs = (Xp) + (size_t)(m0 + lr) * D_ + (kc) + seg * 32;   \
        const __half* ws = (Wp) + (size_t)(n0 + lr) * D_ + (kc) + seg * 32;   \
        unsigned da = sptr(As + (stg)*STG + lr*PB + seg*64);                  \
        unsigned db = sptr(Bs + (stg)*STG + lr*PB + seg*64);                  \
        _Pragma("unroll")                                                     \
        for (int u = 0; u < 4; u++) {                                         \
            CP16(da + u*16, xs + u*8);                                        \
            CP16(db + u*16, ws + u*8);                                        \
        }                                                                     \
        CPCOMMIT;                                                             \
    } while (0)

// single-barrier mainloop: at chunk c the bar (placed after compute c-1)
// makes buffer stg^1 (used at c-1) safe to overwrite with chunk c+1.
#define GEMM_BODY(Xp, Wp)                                                     \
    unsigned aA[2], aB[4];                                                    \
    _Pragma("unroll")                                                         \
    for (int mt = 0; mt < 2; mt++)                                            \
        aA[mt] = sptr(As) + (wm*32 + mt*16 + l8 + b3*8)*PB + b4*16;           \
    _Pragma("unroll")                                                         \
    for (int p = 0; p < 4; p++)                                               \
        aB[p] = sptr(Bs) + (wn*64 + p*16 + l8 + b4*8)*PB + b3*16;             \
    GISSUE(Xp, Wp, 0, 0);                                                     \
    float acc[2][8][4];                                                       \
    _Pragma("unroll")                                                         \
    for (int mt = 0; mt < 2; mt++)                                            \
        _Pragma("unroll")                                                     \
        for (int nt = 0; nt < 8; nt++)                                        \
            _Pragma("unroll")                                                 \
            for (int i2 = 0; i2 < 4; i2++) acc[mt][nt][i2] = 0.f;             \
    for (int c = 0; c < 8; c++) {                                             \
        int stg = c & 1;                                                      \
        CPWAIT0;                                                              \
        __syncthreads();                                                      \
        if (c + 1 < 8) GISSUE(Xp, Wp, (c+1)*64, stg ^ 1);                     \
        _Pragma("unroll")                                                     \
        for (int ks = 0; ks < 4; ks++) {                                      \
            unsigned off = (unsigned)stg*STG + ks*32;                         \
            unsigned a0[4], a1[4];                                            \
            ldsm4(a0, aA[0] + off);                                           \
            ldsm4(a1, aA[1] + off);                                           \
            _Pragma("unroll")                                                 \
            for (int p = 0; p < 4; p++) {                                     \
                unsigned bb[4];                                               \
                ldsm4(bb, aB[p] + off);                                       \
                mma16(acc[0][2*p],   a0, bb);                                 \
                mma16(acc[1][2*p],   a1, bb);                                 \
                mma16(acc[0][2*p+1], a0, bb + 2);                             \
                mma16(acc[1][2*p+1], a1, bb + 2);                             \
            }                                                                 \
        }                                                                     \
    }

// ---------------------------------------------------------------------------
// QKV projection: -> Q,K,V fp16 [B,H,S,Dh]; Q * 0.125*log2(e)
// ---------------------------------------------------------------------------
__global__ __launch_bounds__(256, 2) void qkv_kernel(const float* __restrict__ bias) {
    extern __shared__ char smc[];
    char* As = smc;
    char* Bs = smc + 2*STG;

    int tid = threadIdx.x;
    int m0 = blockIdx.y * 128, n0 = blockIdx.x * 128;
    int w = tid >> 5, lane = tid & 31;
    int wm = w >> 1, wn = w & 1;
    int g = lane >> 2, tg = lane & 3;
    int lr = tid >> 1, seg = tid & 1;
    int l8 = lane & 7, b3 = (lane >> 3) & 1, b4 = lane >> 4;

    GEMM_BODY(g_X, g_Wi)

    int sec = n0 >> 9;
    __half* dst = (sec == 0) ? g_Q : (sec == 1 ? g_K : g_V);
    float qs = (sec == 0) ? 0.125f * 1.4426950408889634f : 1.0f;
#pragma unroll
    for (int mt = 0; mt < 2; mt++) {
#pragma unroll
        for (int hf = 0; hf < 2; hf++) {
            int mm = m0 + wm * 32 + mt * 16 + g + hf * 8;
            int bb = mm >> 11, ss = mm & (S_ - 1);
#pragma unroll
            for (int nt = 0; nt < 8; nt++) {
                int col = n0 + wn * 64 + nt * 8 + 2 * tg;
                float2 bi = *(const float2*)(bias + col);
                float v0 = (acc[mt][nt][hf * 2 + 0] + bi.x) * qs;
                float v1 = (acc[mt][nt][hf * 2 + 1] + bi.y) * qs;
                int d = col & (D_ - 1);
                int hh = d >> 6, dh = d & 63;
                __half* p = dst + (((size_t)(bb * H_ + hh)) * S_ + ss) * DH_ + dh;
                *(unsigned*)p = h2u(v0, v1);
            }
        }
    }
}

// ---------------------------------------------------------------------------
// Output projection: out(fp32) = g_O(fp16) @ g_Wo^T + b_out
// ---------------------------------------------------------------------------
__global__ __launch_bounds__(256, 2) void out_kernel(const float* __restrict__ bias,
                                                     float* __restrict__ out) {
    extern __shared__ char smc[];
    char* As = smc;
    char* Bs = smc + 2*STG;

    int tid = threadIdx.x;
    int m0 = blockIdx.y * 128, n0 = blockIdx.x * 128;
    int w = tid >> 5, lane = tid & 31;
    int wm = w >> 1, wn = w & 1;
    int g = lane >> 2, tg = lane & 3;
    int lr = tid >> 1, seg = tid & 1;
    int l8 = lane & 7, b3 = (lane >> 3) & 1, b4 = lane >> 4;

    GEMM_BODY(g_O, g_Wo)

#pragma unroll
    for (int mt = 0; mt < 2; mt++) {
#pragma unroll
        for (int hf = 0; hf < 2; hf++) {
            int mm = m0 + wm * 32 + mt * 16 + g + hf * 8;
#pragma unroll
            for (int nt = 0; nt < 8; nt++) {
                int col = n0 + wn * 64 + nt * 8 + 2 * tg;
                float2 bi = *(const float2*)(bias + col);
                *(float2*)&out[(size_t)mm * D_ + col] =
                    make_float2(acc[mt][nt][hf * 2 + 0] + bi.x,
                                acc[mt][nt][hf * 2 + 1] + bi.y);
            }
        }
    }
}

// ---------------------------------------------------------------------------
// Flash attention, fp16 mma. Double-buffered K/V, ONE bar per tile.
// P stays entirely in registers (S-accum layout == PV A-frag layout).
// ---------------------------------------------------------------------------
#define AP  144            // byte pitch
#define KTB (64*AP)        // 9216 B per K or V buffer

__global__ __launch_bounds__(128, 2) void attn_kernel() {
    extern __shared__ char smc[];
    char* SP = smc;                   // 128 rows: Q (prologue only)
    char* KB = smc + 128*AP;          // 2 x 64 rows
    char* VB = KB + 2*KTB;            // 2 x 64 rows

    int qt = blockIdx.x, h = blockIdx.y, b = blockIdx.z;
    const __half* Qg = g_Q + (((size_t)(b * H_ + h)) * S_ + qt * QT_) * DH_;
    const __half* Kg = g_K + ((size_t)(b * H_ + h)) * S_ * DH_;
    const __half* Vg = g_V + ((size_t)(b * H_ + h)) * S_ * DH_;

    int tid = threadIdx.x, w = tid >> 5, lane = tid & 31;
    int g = lane >> 2, tg = lane & 3;
    int l8 = lane & 7, b3 = (lane >> 3) & 1, b4 = lane >> 4;
    int r0 = w * 32;

    unsigned aSP[2], aK[4], aV[4];
#pragma unroll
    for (int f = 0; f < 2; f++)
        aSP[f] = sptr(SP) + (r0 + f*16 + l8 + b3*8)*AP + b4*16;
#pragma unroll
    for (int p = 0; p < 4; p++) {
        aK[p] = sptr(KB) + (p*16 + l8 + b4*8)*AP + b3*16;
        aV[p] = sptr(VB) + (l8 + b3*8)*AP + p*32 + b4*16;
    }

    // prologue: Q -> SP ; K0+V0 -> buffers 0
#pragma unroll
    for (int p = 0; p < 8; p++) {
        int slot = tid + p * 128, row = slot >> 3, u = slot & 7;
        CP16(sptr(SP + row*AP + u*16), Qg + row * DH_ + u * 8);
    }
    CPCOMMIT;
#pragma unroll
    for (int p = 0; p < 4; p++) {
        int slot = tid + p * 128, row = slot >> 3, u = slot & 7;
        CP16(sptr(KB + row*AP + u*16), Kg + row * DH_ + u * 8);
        CP16(sptr(VB + row*AP + u*16), Vg + row * DH_ + u * 8);
    }
    CPCOMMIT;
    CPWAIT1;
    __syncthreads();

    unsigned qf[2][4][4];
#pragma unroll
    for (int f = 0; f < 2; f++)
#pragma unroll
        for (int ks = 0; ks < 4; ks++)
            ldsm4(qf[f][ks], aSP[f] + ks * 32);

    float oacc[2][8][4];
#pragma unroll
    for (int f = 0; f < 2; f++)
#pragma unroll
        for (int dt = 0; dt < 8; dt++)
#pragma unroll
            for (int i = 0; i < 4; i++) oacc[f][dt][i] = 0.f;
    float mrow[2][2], lrow[2][2];
#pragma unroll
    for (int f = 0; f < 2; f++) {
        mrow[f][0] = -CUDART_INF_F; mrow[f][1] = -CUDART_INF_F;
        lrow[f][0] = 0.f; lrow[f][1] = 0.f;
    }

    for (int kt = 0; kt < NT_; kt++) {
        int cur = kt & 1, nxt = cur ^ 1;
        CPWAIT0;
        __syncthreads();

        // prefetch (K,V)[kt+1]
        {
            int t1 = (kt + 1) & (NT_ - 1);
            const __half* Kt = Kg + (size_t)t1 * 64 * DH_;
            const __half* Vt = Vg + (size_t)t1 * 64 * DH_;
#pragma unroll
            for (int p = 0; p < 4; p++) {
                int slot = tid + p * 128, row = slot >> 3, u = slot & 7;
                CP16(sptr(KB + nxt*KTB + row*AP + u*16), Kt + row * DH_ + u * 8);
                CP16(sptr(VB + nxt*KTB + row*AP + u*16), Vt + row * DH_ + u * 8);
            }
            CPCOMMIT;
        }

        // S = Q K^T
        float s[2][8][4];
#pragma unroll
        for (int f = 0; f < 2; f++)
#pragma unroll
            for (int nt = 0; nt < 8; nt++)
#pragma unroll
                for (int i = 0; i < 4; i++) s[f][nt][i] = 0.f;
#pragma unroll
        for (int ks = 0; ks < 4; ks++) {
            unsigned off = (unsigned)cur*KTB + ks*32;
#pragma unroll
            for (int p = 0; p < 4; p++) {
                unsigned bb[4];
                ldsm4(bb, aK[p] + off);
                mma16(s[0][2*p],   qf[0][ks], bb);
                mma16(s[1][2*p],   qf[1][ks], bb);
                mma16(s[0][2*p+1], qf[0][ks], bb + 2);
                mma16(s[1][2*p+1], qf[1][ks], bb + 2);
            }
        }

        // online softmax (exp2 domain) — P stays in registers
#pragma unroll
        for (int f = 0; f < 2; f++) {
            float mxl = -CUDART_INF_F, mxh = -CUDART_INF_F;
#pragma unroll
            for (int nt = 0; nt < 8; nt++) {
                mxl = fmaxf(mxl, fmaxf(s[f][nt][0], s[f][nt][1]));
                mxh = fmaxf(mxh, fmaxf(s[f][nt][2], s[f][nt][3]));
            }
            mxl = fmaxf(mxl, __shfl_xor_sync(0xffffffffu, mxl, 1));
            mxl = fmaxf(mxl, __shfl_xor_sync(0xffffffffu, mxl, 2));
            mxh = fmaxf(mxh, __shfl_xor_sync(0xffffffffu, mxh, 1));
            mxh = fmaxf(mxh, __shfl_xor_sync(0xffffffffu, mxh, 2));
            float mnl = fmaxf(mrow[f][0], mxl), mnh = fmaxf(mrow[f][1], mxh);
            float al = ex2f(mrow[f][0] - mnl), ah = ex2f(mrow[f][1] - mnh);
            mrow[f][0] = mnl; mrow[f][1] = mnh;
            float rsl = 0.f, rsh = 0.f;
#pragma unroll
            for (int nt = 0; nt < 8; nt++) {
                s[f][nt][0] = ex2f(s[f][nt][0] - mnl);
                s[f][nt][1] = ex2f(s[f][nt][1] - mnl);
                s[f][nt][2] = ex2f(s[f][nt][2] - mnh);
                s[f][nt][3] = ex2f(s[f][nt][3] - mnh);
                rsl += s[f][nt][0] + s[f][nt][1];
                rsh += s[f][nt][2] + s[f][nt][3];
            }
            rsl += __shfl_xor_sync(0xffffffffu, rsl, 1);
            rsl += __shfl_xor_sync(0xffffffffu, rsl, 2);
            rsh += __shfl_xor_sync(0xffffffffu, rsh, 1);
            rsh += __shfl_xor_sync(0xffffffffu, rsh, 2);
            lrow[f][0] = lrow[f][0] * al + rsl;
            lrow[f][1] = lrow[f][1] * ah + rsh;
#pragma unroll
            for (int dt = 0; dt < 8; dt++) {
                oacc[f][dt][0] *= al; oacc[f][dt][1] *= al;
                oacc[f][dt][2] *= ah; oacc[f][dt][3] *= ah;
            }
        }

        // O += P V : P A-frags in-register; V B-frags via ldmatrix.trans
#pragma unroll
        for (int ks = 0; ks < 4; ks++) {
            unsigned pa[2][4];
#pragma unroll
            for (int f = 0; f < 2; f++) {
                pa[f][0] = h2u(s[f][2*ks][0],   s[f][2*ks][1]);
                pa[f][1] = h2u(s[f][2*ks][2],   s[f][2*ks][3]);
                pa[f][2] = h2u(s[f][2*ks+1][0], s[f][2*ks+1][1]);
                pa[f][3] = h2u(s[f][2*ks+1][2], s[f][2*ks+1][3]);
            }
            unsigned voff = (unsigned)cur*KTB + ks*16*AP;
#pragma unroll
            for (int p = 0; p < 4; p++) {
                unsigned vb[4];
                ldsm4t(vb, aV[p] + voff);
                mma16(oacc[0][2*p],   pa[0], vb);
                mma16(oacc[1][2*p],   pa[1], vb);
                mma16(oacc[0][2*p+1], pa[0], vb + 2);
                mma16(oacc[1][2*p+1], pa[1], vb + 2);
            }
        }
    }

    // epilogue
    __half* Og = g_O + ((size_t)(b * S_ + qt * QT_)) * D_ + h * DH_;
#pragma unroll
    for (int f = 0; f < 2; f++) {
        float il = 1.0f / lrow[f][0], ih = 1.0f / lrow[f][1];
        int rl = r0 + f * 16 + g, rh = rl + 8;
#pragma unroll
        for (int dt = 0; dt < 8; dt++) {
            int c = dt * 8 + 2 * tg;
            *(unsigned*)&Og[(size_t)rl * D_ + c] = h2u(oacc[f][dt][0] * il, oacc[f][dt][1] * il);
            *(unsigned*)&Og[(size_t)rh * D_ + c] = h2u(oacc[f][dt][2] * ih, oacc[f][dt][3] * ih);
        }
    }
}

// ---------------------------------------------------------------------------
extern "C" void kernel_launch(void* const* d_in, const int* in_sizes, int n_in,
                              void* d_out, int out_size) {
    const float* x     = (const float*)d_in[0];
    const float* w_in  = (const float*)d_in[1];
    const float* b_in  = (const float*)d_in[2];
    const float* w_out = (const float*)d_in[3];
    const float* b_out = (const float*)d_in[4];
    float* out = (float*)d_out;

    const int gemm_smem = 4 * STG;                    // 73728 B
    const int attn_smem = 128*AP + 4*KTB;             // 55296 B
    cudaFuncSetAttribute(qkv_kernel,  cudaFuncAttributeMaxDynamicSharedMemorySize, gemm_smem);
    cudaFuncSetAttribute(out_kernel,  cudaFuncAttributeMaxDynamicSharedMemorySize, gemm_smem);
    cudaFuncSetAttribute(attn_kernel, cudaFuncAttributeMaxDynamicSharedMemorySize, attn_smem);

    __half* gx;  cudaGetSymbolAddress((void**)&gx,  g_X);
    __half* gwi; cudaGetSymbolAddress((void**)&gwi, g_Wi);
    __half* gwo; cudaGetSymbolAddress((void**)&gwo, g_Wo);
    int tot4 = XN4 + WIN4 + WON4;
    round_kernel<<<(tot4 + 255) / 256, 256>>>(
        (const float4*)x, (const float4*)w_in, (const float4*)w_out,
        (uint2*)gx, (uint2*)gwi, (uint2*)gwo);

    qkv_kernel<<<dim3(12, 128), 256, gemm_smem>>>(b_in);
    attn_kernel<<<dim3(S_ / QT_, H_, B_), 128, attn_smem>>>();
    out_kernel<<<dim3(4, 128), 256, gemm_smem>>>(b_out, out);
}